// round 6
// baseline (speedup 1.0000x reference)
#include <cuda_runtime.h>
#include <cuda_bf16.h>
#include <cstdint>
#include <cstddef>

namespace {
constexpr int T = 1000, B = 256, I = 700, H = 256, O = 20, WHS = I + H;
constexpr float DELTA = 0.01f, GAMMA = 0.9f, THETA = 1.0f;
constexpr size_t OFF_LOSS = (size_t)T * B * O;
constexpr size_t OFF_ZF = OFF_LOSS + 1;
constexpr size_t OFF_UF = OFF_ZF + (size_t)B * H;
constexpr size_t OFF_OUF = OFF_UF + (size_t)B * H;

// ---- recurrence kernel smem layout (float offsets) ----
constexpr int SM_ZB = 0;
constexpr int SM_WS = 2048;
constexpr int SM_COMB = SM_WS + 32768;
constexpr int SM_WOT = SM_COMB + 512;
constexpr int SM_POUA = SM_WOT + 2560;
constexpr int SM_POUB = SM_POUA + 160;
constexpr int SM_OUS = SM_POUB + 160;
constexpr int SM_AL = SM_OUS + 80;
constexpr int SM_TOT = SM_AL + 32;

// ---- mma.sync GEMM config (128x128 CTA, warp 32x64, no spills) ----
constexpr int NCH = 22;                 // K chunks of 32 (K padded to 704)
constexpr int WIMG = 256 * 64;          // 16 KB: one (term,chunk) W image
// stage byte offsets (per 32 KB stage)
constexpr int AHI = 0;                  // [128 rows][64B] swizzled
constexpr int ALO = 8192;
constexpr int BHI = 16384;              // [128 rows][64B] swizzled (this CTA's N half)
constexpr int BLO = 24576;
constexpr int STAGE = 32768;
constexpr int GS_TOTAL = 2 * STAGE;     // 64 KB
}  // namespace

__device__ float g_curx[(size_t)T * B * H];  // x @ W_x^T
__device__ float g_loss[B];
__device__ __align__(128) unsigned char g_wB[2 * NCH * WIMG];  // [term][chunk] images

// ---------------------------------------------------------------------------
// helpers
// ---------------------------------------------------------------------------
__device__ __forceinline__ unsigned smem_u32(const void* p) {
  return (unsigned)__cvta_generic_to_shared(p);
}
__device__ __forceinline__ void cluster_sync_all() {
  asm volatile("barrier.cluster.arrive.aligned;" ::: "memory");
  asm volatile("barrier.cluster.wait.aligned;" ::: "memory");
}
__device__ __forceinline__ unsigned mapa_rank(unsigned a, unsigned r) {
  unsigned o;
  asm("mapa.shared::cluster.u32 %0, %1, %2;" : "=r"(o) : "r"(a), "r"(r));
  return o;
}
__device__ __forceinline__ void stc_f32(unsigned a, float v) {
  asm volatile("st.shared::cluster.f32 [%0], %1;" :: "r"(a), "f"(v) : "memory");
}

#define LDSM4(r, addr)                                                        \
  asm volatile("ldmatrix.sync.aligned.m8n8.x4.shared.b16 {%0,%1,%2,%3}, [%4];" \
               : "=r"((r)[0]), "=r"((r)[1]), "=r"((r)[2]), "=r"((r)[3])        \
               : "r"(addr))

#define MMA16816(d, a, b0, b1)                                                \
  asm volatile(                                                               \
      "mma.sync.aligned.m16n8k16.row.col.f32.bf16.bf16.f32 "                  \
      "{%0,%1,%2,%3},{%4,%5,%6,%7},{%8,%9},{%0,%1,%2,%3};"                    \
      : "+f"((d)[0]), "+f"((d)[1]), "+f"((d)[2]), "+f"((d)[3])                \
      : "r"((a)[0]), "r"((a)[1]), "r"((a)[2]), "r"((a)[3]), "r"(b0), "r"(b1))

#define CPASYNC16(dst, src)                                                   \
  asm volatile("cp.async.cg.shared.global [%0], [%1], 16;" :: "r"(dst),       \
               "l"(src) : "memory")

// ---------------------------------------------------------------------------
// Kernel 0: split W_h[:, :700] into bf16 hi/lo, pre-swizzled smem-image layout
// image[n][cSw][8 bf16], cSw = c ^ ((n>>1)&3). One block per (term, chunk).
// ---------------------------------------------------------------------------
__global__ void prep_w_kernel(const float* __restrict__ Wh) {
  const int chunk = blockIdx.x % NCH;
  const int term = blockIdx.x / NCH;  // 0 = hi, 1 = lo
  const int n = threadIdx.x;          // 0..255
  unsigned char* dst = g_wB + (size_t)(term * NCH + chunk) * WIMG + n * 64;
#pragma unroll
  for (int c = 0; c < 4; ++c) {
    uint32_t u[4];
#pragma unroll
    for (int jj = 0; jj < 4; ++jj) {
      const int k = chunk * 32 + c * 8 + jj * 2;
      float w0 = (k < I) ? Wh[(size_t)n * WHS + k] : 0.f;
      float w1 = (k + 1 < I) ? Wh[(size_t)n * WHS + k + 1] : 0.f;
      __nv_bfloat16 h0 = __float2bfloat16(w0), h1 = __float2bfloat16(w1);
      if (term) {
        h0 = __float2bfloat16(w0 - __bfloat162float(h0));
        h1 = __float2bfloat16(w1 - __bfloat162float(h1));
      }
      u[jj] = (uint32_t)__bfloat16_as_ushort(h0) |
              ((uint32_t)__bfloat16_as_ushort(h1) << 16);
    }
    const int cSw = c ^ ((n >> 1) & 3);
    *reinterpret_cast<uint4*>(dst + cSw * 16) = make_uint4(u[0], u[1], u[2], u[3]);
  }
}

// ---------------------------------------------------------------------------
// A-chunk STS: convert this thread's 32 f32 (row arow, k aseg..aseg+15 x2) to
// bf16 hi/lo and store swizzled.
// ---------------------------------------------------------------------------
__device__ __forceinline__ void sts_a_chunk(unsigned char* stg, const float4* av,
                                            int aseg, uint32_t aXor, uint32_t aDst) {
#pragma unroll
  for (int half = 0; half < 2; ++half) {
    const float4 p = av[2 * half];
    const float4 q = av[2 * half + 1];
    const float fs[8] = {p.x, p.y, p.z, p.w, q.x, q.y, q.z, q.w};
    uint32_t hu[4], lu[4];
#pragma unroll
    for (int jj = 0; jj < 4; ++jj) {
      __nv_bfloat16 h0 = __float2bfloat16(fs[2 * jj]);
      __nv_bfloat16 h1 = __float2bfloat16(fs[2 * jj + 1]);
      __nv_bfloat16 l0 = __float2bfloat16(fs[2 * jj] - __bfloat162float(h0));
      __nv_bfloat16 l1 = __float2bfloat16(fs[2 * jj + 1] - __bfloat162float(h1));
      hu[jj] = (uint32_t)__bfloat16_as_ushort(h0) |
               ((uint32_t)__bfloat16_as_ushort(h1) << 16);
      lu[jj] = (uint32_t)__bfloat16_as_ushort(l0) |
               ((uint32_t)__bfloat16_as_ushort(l1) << 16);
    }
    const int cc = (aseg >> 3) + half;
    const uint32_t off = aDst + ((uint32_t)(cc ^ aXor) << 4);
    *reinterpret_cast<uint4*>(stg + AHI + off) = make_uint4(hu[0], hu[1], hu[2], hu[3]);
    *reinterpret_cast<uint4*>(stg + ALO + off) = make_uint4(lu[0], lu[1], lu[2], lu[3]);
  }
}

// ---------------------------------------------------------------------------
// Kernel 1: cur_x = x @ W_x^T via mma.sync bf16, 3-term hi/lo split.
// CTA: 128(M) x 128(N half), 8 warps (4m x 2n), warp tile 32x64.
// acc[2][8][4] = 64 regs -> no spills.
// ---------------------------------------------------------------------------
__global__ __launch_bounds__(256) void gemm_mma_kernel(const float* __restrict__ X) {
  extern __shared__ __align__(1024) unsigned char smem[];
  const uint32_t sb = smem_u32(smem);
  const int tid = threadIdx.x;
  const int lane = tid & 31, wid = tid >> 5;
  const int wm = (wid & 3) * 32, wn = (wid >> 2) * 64;
  const int bx = blockIdx.x;
  const int m0 = (bx >> 1) * 128;
  const int n0 = (bx & 1) * 128;       // this CTA's half of H

  // A loader: row = tid>>1 (0..127), kseg = (tid&1)*16
  const int arow = tid >> 1;
  const int aseg = (tid & 1) << 4;
  const float* xrow = X + (size_t)(m0 + arow) * I;
  const uint32_t aXor = ((arow >> 1) & 3);
  const uint32_t aDst = (uint32_t)(arow * 64);

  // ldmatrix per-lane address components (local rows)
  int ra[2], sa[2], rb[4], sxb[4];
#pragma unroll
  for (int mt = 0; mt < 2; ++mt) {
    int r = wm + mt * 16 + (lane & 15);
    ra[mt] = r * 64;
    sa[mt] = (r >> 1) & 3;
  }
  const int ca = lane >> 4;
#pragma unroll
  for (int g = 0; g < 4; ++g) {
    int n = wn + g * 16 + (lane & 7) + ((lane >> 4) << 3);
    rb[g] = n * 64;
    sxb[g] = (n >> 1) & 3;
  }
  const int cbsel = (lane >> 3) & 1;

  float acc[2][8][4];
#pragma unroll
  for (int mt = 0; mt < 2; ++mt)
#pragma unroll
    for (int n8 = 0; n8 < 8; ++n8)
#pragma unroll
      for (int j = 0; j < 4; ++j) acc[mt][n8][j] = 0.f;

  float4 av[4];

  // ---- prologue: chunk 0 ----
#pragma unroll
  for (int i = 0; i < 4; ++i) {
    const int col = aseg + i * 4;
    av[i] = (col < I) ? *reinterpret_cast<const float4*>(xrow + col)
                      : make_float4(0.f, 0.f, 0.f, 0.f);
  }
  {
    const unsigned char* srcH = g_wB + n0 * 64;                       // chunk0 hi
    const unsigned char* srcL = g_wB + (size_t)NCH * WIMG + n0 * 64;  // chunk0 lo
#pragma unroll
    for (int i = 0; i < 2; ++i) {
      CPASYNC16(sb + BHI + tid * 16 + i * 4096, srcH + tid * 16 + i * 4096);
      CPASYNC16(sb + BLO + tid * 16 + i * 4096, srcL + tid * 16 + i * 4096);
    }
    asm volatile("cp.async.commit_group;" ::: "memory");
  }
  sts_a_chunk(smem, av, aseg, aXor, aDst);

  // ---- main loop ----
  for (int c = 0; c < NCH; ++c) {
    asm volatile("cp.async.wait_group 0;" ::: "memory");
    __syncthreads();

    const int nc = c + 1;
    if (nc < NCH) {
      const uint32_t nst = sb + (nc & 1) * STAGE;
      const unsigned char* srcH = g_wB + (size_t)nc * WIMG + n0 * 64;
      const unsigned char* srcL = g_wB + (size_t)(NCH + nc) * WIMG + n0 * 64;
#pragma unroll
      for (int i = 0; i < 2; ++i) {
        CPASYNC16(nst + BHI + tid * 16 + i * 4096, srcH + tid * 16 + i * 4096);
        CPASYNC16(nst + BLO + tid * 16 + i * 4096, srcL + tid * 16 + i * 4096);
      }
      asm volatile("cp.async.commit_group;" ::: "memory");
      const int colbase = nc * 32 + aseg;
#pragma unroll
      for (int i = 0; i < 4; ++i) {
        const int col = colbase + i * 4;
        av[i] = (col < I) ? *reinterpret_cast<const float4*>(xrow + col)
                          : make_float4(0.f, 0.f, 0.f, 0.f);
      }
    }

    // ---- compute chunk c (3 terms, b-hi reused before b-lo overwrites) ----
    const uint32_t st = sb + (c & 1) * STAGE;
#pragma unroll
    for (int k16 = 0; k16 < 2; ++k16) {
      uint32_t ah[2][4], al[2][4], bb[4][4];
      const int kca = k16 * 2 + ca;
      const int kcb = k16 * 2 + cbsel;
#pragma unroll
      for (int mt = 0; mt < 2; ++mt)
        LDSM4(ah[mt], st + AHI + ra[mt] + (((kca ^ sa[mt])) << 4));
#pragma unroll
      for (int g = 0; g < 4; ++g)
        LDSM4(bb[g], st + BHI + rb[g] + (((kcb ^ sxb[g])) << 4));
#pragma unroll
      for (int mt = 0; mt < 2; ++mt)
#pragma unroll
        for (int g = 0; g < 4; ++g) {
          MMA16816(acc[mt][2 * g], ah[mt], bb[g][0], bb[g][1]);
          MMA16816(acc[mt][2 * g + 1], ah[mt], bb[g][2], bb[g][3]);
        }
#pragma unroll
      for (int mt = 0; mt < 2; ++mt)
        LDSM4(al[mt], st + ALO + ra[mt] + (((kca ^ sa[mt])) << 4));
#pragma unroll
      for (int mt = 0; mt < 2; ++mt)
#pragma unroll
        for (int g = 0; g < 4; ++g) {
          MMA16816(acc[mt][2 * g], al[mt], bb[g][0], bb[g][1]);
          MMA16816(acc[mt][2 * g + 1], al[mt], bb[g][2], bb[g][3]);
        }
#pragma unroll
      for (int g = 0; g < 4; ++g)
        LDSM4(bb[g], st + BLO + rb[g] + (((kcb ^ sxb[g])) << 4));
#pragma unroll
      for (int mt = 0; mt < 2; ++mt)
#pragma unroll
        for (int g = 0; g < 4; ++g) {
          MMA16816(acc[mt][2 * g], ah[mt], bb[g][0], bb[g][1]);
          MMA16816(acc[mt][2 * g + 1], ah[mt], bb[g][2], bb[g][3]);
        }
    }

    if (nc < NCH)
      sts_a_chunk(smem + (nc & 1) * STAGE, av, aseg, aXor, aDst);
  }

  // ---- epilogue: acc -> g_curx ----
#pragma unroll
  for (int mt = 0; mt < 2; ++mt) {
    const int r0 = m0 + wm + mt * 16 + (lane >> 2);
#pragma unroll
    for (int n8 = 0; n8 < 8; ++n8) {
      const int col = n0 + wn + n8 * 8 + (lane & 3) * 2;
      *reinterpret_cast<float2*>(g_curx + (size_t)r0 * H + col) =
          make_float2(acc[mt][n8][0], acc[mt][n8][1]);
      *reinterpret_cast<float2*>(g_curx + (size_t)(r0 + 8) * H + col) =
          make_float2(acc[mt][n8][2], acc[mt][n8][3]);
    }
  }
}

// ---------------------------------------------------------------------------
// Kernel 2: persistent BRF recurrence (unchanged — passing)
// ---------------------------------------------------------------------------
__global__ void __cluster_dims__(2, 1, 1) __launch_bounds__(256, 1)
rec_kernel(const float* __restrict__ Wh, const float* __restrict__ omp,
           const float* __restrict__ bop, const float* __restrict__ Wo,
           const float* __restrict__ taup, const int* __restrict__ Y,
           float* __restrict__ out) {
  extern __shared__ float sm[];
  float4* zb = reinterpret_cast<float4*>(sm + SM_ZB);
  float* Ws = sm + SM_WS;
  float* comb = sm + SM_COMB;
  float* WoT = sm + SM_WOT;
  float* pouA = sm + SM_POUA;
  float* pouB = sm + SM_POUB;
  float* ous = sm + SM_OUS;
  float* alph = sm + SM_AL;

  const int tid = threadIdx.x;
  unsigned rank;
  asm("mov.u32 %0, %%cluster_ctarank;" : "=r"(rank));
  const int cl = blockIdx.x >> 1, row0 = cl * 4;

  for (int i = tid; i < 32768; i += 256) {
    int j = i >> 7, hl = i & 127;
    Ws[i] = Wh[(size_t)((int)rank * 128 + hl) * WHS + I + j];
  }
  for (int i = tid; i < 2560; i += 256) {
    int hl = i / 20, o = i - hl * 20;
    WoT[i] = Wo[o * H + (int)rank * 128 + hl];
  }
  if (tid < O) alph[tid] = expf(-DELTA / taup[tid]);
  for (int i = tid; i < 512; i += 256) zb[i] = make_float4(0.f, 0.f, 0.f, 0.f);
  for (int i = tid; i < 160; i += 256) { pouA[i] = 0.f; pouB[i] = 0.f; }
  for (int i = tid; i < 80; i += 256) ous[i] = 0.f;

  const int h = tid & 127, half = tid >> 7;
  float om = 0.f, pom = 0.f, bof = 0.f;
  float u[4] = {0, 0, 0, 0}, v[4] = {0, 0, 0, 0}, q[4] = {0, 0, 0, 0},
        zr[4] = {0, 0, 0, 0};
  if (tid < 128) {
    int hg = (int)rank * 128 + tid;
    om = fabsf(omp[hg]);
    float dm = DELTA * om;
    pom = (-1.f + sqrtf(1.f - dm * dm)) / DELTA;
    bof = fabsf(bop[hg]);
  }
  float lossacc = 0.f;
  int yprev = 0;

  const unsigned zrem = mapa_rank(smem_u32(zb), rank ^ 1u);
  const unsigned prem = mapa_rank(smem_u32(pouB), 0u);

  __syncthreads();
  cluster_sync_all();

  for (int t = 0; t < T; ++t) {
    const int cb2 = t & 1, nb = cb2 ^ 1;

    if (rank == 0 && tid < 4) {
      int ynew = Y[t * B + row0 + tid];
      if (t > 0) {
        const int pb = cb2 ^ 1;
        const float* pa = pouA + pb * 80 + tid * 20;
        const float* pbp = pouB + pb * 80 + tid * 20;
        float m = -1e30f, ly = 0.f;
        for (int o = 0; o < O; ++o) {
          float a = alph[o];
          float s = ous[tid * 20 + o] * a + (1.f - a) * (pa[o] + pbp[o]);
          ous[tid * 20 + o] = s;
          out[(size_t)(t - 1) * B * O + (size_t)(row0 + tid) * O + o] = s;
          m = fmaxf(m, s);
          if (o == yprev) ly = s;
        }
        float se = 0.f;
        for (int o = 0; o < O; ++o) se += expf(ous[tid * 20 + o] - m);
        lossacc += -(ly - m - logf(se)) * (1.f / (float)B);
      }
      yprev = ynew;
    }

    float c0 = 0.f, c1 = 0.f, c2 = 0.f, c3 = 0.f;
    if (tid < 128) {
      const float* cp = g_curx + ((size_t)t * B + row0) * H + (int)rank * 128 + tid;
      c0 = cp[0]; c1 = cp[H]; c2 = cp[2 * H]; c3 = cp[3 * H];
    }

    float a0 = 0.f, a1 = 0.f, a2 = 0.f, a3 = 0.f;
    {
      const float4* zrow = zb + cb2 * 256 + half * 128;
      const float* wc = Ws + half * 128 * 128 + h;
#pragma unroll 16
      for (int j = 0; j < 128; ++j) {
        float w = wc[j * 128];
        float4 z4 = zrow[j];
        a0 += w * z4.x; a1 += w * z4.y; a2 += w * z4.z; a3 += w * z4.w;
      }
    }
    if (half) {
      comb[h] = a0; comb[128 + h] = a1; comb[256 + h] = a2; comb[384 + h] = a3;
    }
    __syncthreads();

    if (tid < 128) {
      float cw[4] = {c0 + a0 + comb[tid], c1 + a1 + comb[128 + tid],
                     c2 + a2 + comb[256 + tid], c3 + a3 + comb[384 + tid]};
#pragma unroll
      for (int rr = 0; rr < 4; ++rr) {
        float b = pom - bof - q[rr];
        float un = u[rr] + DELTA * (b * u[rr] - om * v[rr] + cw[rr]);
        float vn = v[rr] + DELTA * (om * un + b * v[rr]);
        float z = (un - THETA - q[rr]) > 0.f ? 1.f : 0.f;
        q[rr] = GAMMA * q[rr] + z;
        u[rr] = un; v[rr] = vn; zr[rr] = z;
      }
      int jg = (int)rank * 128 + tid;
      zb[nb * 256 + jg] = make_float4(zr[0], zr[1], zr[2], zr[3]);
      unsigned pa = zrem + (unsigned)(nb * 256 + jg) * 16u;
      stc_f32(pa, zr[0]); stc_f32(pa + 4, zr[1]);
      stc_f32(pa + 8, zr[2]); stc_f32(pa + 12, zr[3]);
    }
    __syncthreads();

    if (tid < 80) {
      int rr = tid / 20, o = tid - rr * 20;
      const float* zz = sm + SM_ZB + (size_t)(nb * 256 + (int)rank * 128) * 4 + rr;
      float s = 0.f;
#pragma unroll 8
      for (int jj = 0; jj < 128; ++jj) s += zz[jj * 4] * WoT[jj * 20 + o];
      if (rank == 0) pouA[cb2 * 80 + tid] = s;
      else stc_f32(prem + (unsigned)(cb2 * 80 + tid) * 4u, s);
    }

    cluster_sync_all();
  }

  if (rank == 0 && tid < 4) {
    const int pb = (T - 1) & 1;
    const float* pa = pouA + pb * 80 + tid * 20;
    const float* pbp = pouB + pb * 80 + tid * 20;
    float m = -1e30f, ly = 0.f;
    for (int o = 0; o < O; ++o) {
      float a = alph[o];
      float s = ous[tid * 20 + o] * a + (1.f - a) * (pa[o] + pbp[o]);
      ous[tid * 20 + o] = s;
      out[(size_t)(T - 1) * B * O + (size_t)(row0 + tid) * O + o] = s;
      m = fmaxf(m, s);
      if (o == yprev) ly = s;
    }
    float se = 0.f;
    for (int o = 0; o < O; ++o) se += expf(ous[tid * 20 + o] - m);
    lossacc += -(ly - m - logf(se)) * (1.f / (float)B);
    g_loss[row0 + tid] = lossacc;
  }
  __syncthreads();

  if (tid < 128) {
#pragma unroll
    for (int rr = 0; rr < 4; ++rr) {
      size_t idx = (size_t)(row0 + rr) * H + (int)rank * 128 + tid;
      out[OFF_ZF + idx] = zr[rr];
      out[OFF_UF + idx] = u[rr];
    }
  }
  if (rank == 0 && tid < 80) {
    int rr = tid / 20, o = tid - rr * 20;
    out[OFF_OUF + (size_t)(row0 + rr) * O + o] = ous[tid];
  }
}

// ---------------------------------------------------------------------------
// Kernel 3: deterministic loss reduction
// ---------------------------------------------------------------------------
__global__ void loss_sum_kernel(float* __restrict__ out) {
  __shared__ float s[256];
  s[threadIdx.x] = g_loss[threadIdx.x];
  __syncthreads();
  for (int st = 128; st > 0; st >>= 1) {
    if (threadIdx.x < st) s[threadIdx.x] += s[threadIdx.x + st];
    __syncthreads();
  }
  if (threadIdx.x == 0) out[OFF_LOSS] = s[0];
}

// ---------------------------------------------------------------------------
extern "C" void kernel_launch(void* const* d_in, const int* in_sizes, int n_in,
                              void* d_out, int out_size) {
  const float* x = (const float*)d_in[0];
  const int* y = (const int*)d_in[1];
  const float* Wh = (const float*)d_in[2];
  const float* omega = (const float*)d_in[3];
  const float* boff = (const float*)d_in[4];
  const float* Wo = (const float*)d_in[5];
  const float* tau = (const float*)d_in[6];
  float* out = (float*)d_out;

  cudaFuncSetAttribute(gemm_mma_kernel, cudaFuncAttributeMaxDynamicSharedMemorySize,
                       GS_TOTAL);
  cudaFuncSetAttribute(rec_kernel, cudaFuncAttributeMaxDynamicSharedMemorySize,
                       SM_TOT * (int)sizeof(float));

  prep_w_kernel<<<2 * NCH, 256>>>(Wh);
  gemm_mma_kernel<<<4000, 256, GS_TOTAL>>>(x);
  rec_kernel<<<B / 2, 256, SM_TOT * sizeof(float)>>>(Wh, omega, boff, Wo, tau, y, out);
  loss_sum_kernel<<<1, 256>>>(out);
}

// round 7
// speedup vs baseline: 1.7903x; 1.7903x over previous
#include <cuda_runtime.h>
#include <cuda_bf16.h>
#include <cstdint>
#include <cstddef>

namespace {
constexpr int T = 1000, B = 256, I = 700, H = 256, O = 20, WHS = I + H;
constexpr float DELTA = 0.01f, GAMMA = 0.9f, THETA = 1.0f;
constexpr size_t OFF_LOSS = (size_t)T * B * O;
constexpr size_t OFF_ZF = OFF_LOSS + 1;
constexpr size_t OFF_UF = OFF_ZF + (size_t)B * H;
constexpr size_t OFF_OUF = OFF_UF + (size_t)B * H;

// ---- recurrence kernel smem layout (float offsets) ----
constexpr int SM_ZM = 0;                    // [2][4][8] uint32 spike bitmasks
constexpr int SM_WS = 64;                   // [256][128] W_z half: [j][h_local]
constexpr int SM_WOT = SM_WS + 32768;       // [128][20] W_o half
constexpr int SM_POUA = SM_WOT + 2560;      // [2][80]
constexpr int SM_POUB = SM_POUA + 160;      // [2][80]
constexpr int SM_OUS = SM_POUB + 160;       // [4][20]
constexpr int SM_AL = SM_OUS + 80;          // [20]
constexpr int SM_TOT = SM_AL + 32;

// ---- mma.sync GEMM config (R5 version: 128x256 CTA, x read once) ----
constexpr int NCH = 22;                 // K chunks of 32 (K padded to 704)
constexpr int WIMG = 256 * 64;          // 16 KB: one (term,chunk) W image
constexpr int GA_HI = 0;                // [128 rows][64B] swizzled
constexpr int GA_LO = 8192;
constexpr int GB_HI = 16384;            // [256 rows][64B] swizzled
constexpr int GB_LO = 32768;
constexpr int GSTAGE = 49152;
constexpr int GS_TOTAL = 2 * GSTAGE;    // 96 KB
}  // namespace

__device__ float g_curx[(size_t)T * B * H];  // x @ W_x^T
__device__ float g_loss[B];
__device__ __align__(128) unsigned char g_wB[2 * NCH * WIMG];  // [term][chunk] images

// ---------------------------------------------------------------------------
// helpers
// ---------------------------------------------------------------------------
__device__ __forceinline__ unsigned smem_u32(const void* p) {
  return (unsigned)__cvta_generic_to_shared(p);
}
__device__ __forceinline__ void cluster_sync_all() {
  asm volatile("barrier.cluster.arrive.aligned;" ::: "memory");
  asm volatile("barrier.cluster.wait.aligned;" ::: "memory");
}
__device__ __forceinline__ unsigned mapa_rank(unsigned a, unsigned r) {
  unsigned o;
  asm("mapa.shared::cluster.u32 %0, %1, %2;" : "=r"(o) : "r"(a), "r"(r));
  return o;
}
__device__ __forceinline__ void stc_f32(unsigned a, float v) {
  asm volatile("st.shared::cluster.f32 [%0], %1;" :: "r"(a), "f"(v) : "memory");
}
__device__ __forceinline__ void stc_u32(unsigned a, unsigned v) {
  asm volatile("st.shared::cluster.u32 [%0], %1;" :: "r"(a), "r"(v) : "memory");
}

#define LDSM4(r, addr)                                                        \
  asm volatile("ldmatrix.sync.aligned.m8n8.x4.shared.b16 {%0,%1,%2,%3}, [%4];" \
               : "=r"((r)[0]), "=r"((r)[1]), "=r"((r)[2]), "=r"((r)[3])        \
               : "r"(addr))

#define MMA16816(d, a, b0, b1)                                                \
  asm volatile(                                                               \
      "mma.sync.aligned.m16n8k16.row.col.f32.bf16.bf16.f32 "                  \
      "{%0,%1,%2,%3},{%4,%5,%6,%7},{%8,%9},{%0,%1,%2,%3};"                    \
      : "+f"((d)[0]), "+f"((d)[1]), "+f"((d)[2]), "+f"((d)[3])                \
      : "r"((a)[0]), "r"((a)[1]), "r"((a)[2]), "r"((a)[3]), "r"(b0), "r"(b1))

#define CPASYNC16(dst, src)                                                   \
  asm volatile("cp.async.cg.shared.global [%0], [%1], 16;" :: "r"(dst),       \
               "l"(src) : "memory")

// ---------------------------------------------------------------------------
// Kernel 0: split W_h[:, :700] into bf16 hi/lo, pre-swizzled smem-image layout
// ---------------------------------------------------------------------------
__global__ void prep_w_kernel(const float* __restrict__ Wh) {
  const int chunk = blockIdx.x % NCH;
  const int term = blockIdx.x / NCH;  // 0 = hi, 1 = lo
  const int n = threadIdx.x;          // 0..255
  unsigned char* dst = g_wB + (size_t)(term * NCH + chunk) * WIMG + n * 64;
#pragma unroll
  for (int c = 0; c < 4; ++c) {
    uint32_t u[4];
#pragma unroll
    for (int jj = 0; jj < 4; ++jj) {
      const int k = chunk * 32 + c * 8 + jj * 2;
      float w0 = (k < I) ? Wh[(size_t)n * WHS + k] : 0.f;
      float w1 = (k + 1 < I) ? Wh[(size_t)n * WHS + k + 1] : 0.f;
      __nv_bfloat16 h0 = __float2bfloat16(w0), h1 = __float2bfloat16(w1);
      if (term) {
        h0 = __float2bfloat16(w0 - __bfloat162float(h0));
        h1 = __float2bfloat16(w1 - __bfloat162float(h1));
      }
      u[jj] = (uint32_t)__bfloat16_as_ushort(h0) |
              ((uint32_t)__bfloat16_as_ushort(h1) << 16);
    }
    const int cSw = c ^ ((n >> 1) & 3);
    *reinterpret_cast<uint4*>(dst + cSw * 16) = make_uint4(u[0], u[1], u[2], u[3]);
  }
}

// ---------------------------------------------------------------------------
// Kernel 1: cur_x = x @ W_x^T via mma.sync bf16, 3-term hi/lo split.
// (R5 version verbatim: CTA 128(M) x 256(N), 8 warps, warp tile 64x64)
// ---------------------------------------------------------------------------
__global__ __launch_bounds__(256, 1) void gemm_mma_kernel(const float* __restrict__ X) {
  extern __shared__ __align__(1024) unsigned char smem[];
  const uint32_t sb = smem_u32(smem);
  const int tid = threadIdx.x;
  const int lane = tid & 31, wid = tid >> 5;
  const int wm = (wid & 1) * 64, wn = (wid >> 1) * 64;
  const int m0 = blockIdx.x * 128;

  const int arow = tid >> 1;
  const int aseg = (tid & 1) << 4;
  const float* xrow = X + (size_t)(m0 + arow) * I;
  const uint32_t aXor = ((arow >> 1) & 3);
  const uint32_t aDstBase = (uint32_t)(arow * 64);

  int raddr[4], sxa[4], rbad[4], sxb[4];
#pragma unroll
  for (int mt = 0; mt < 4; ++mt) {
    int r = wm + mt * 16 + (lane & 15);
    raddr[mt] = r * 64;
    sxa[mt] = (r >> 1) & 3;
  }
  const int ca = lane >> 4;
#pragma unroll
  for (int g = 0; g < 4; ++g) {
    int n = wn + g * 16 + (lane & 7) + ((lane >> 4) << 3);
    rbad[g] = n * 64;
    sxb[g] = (n >> 1) & 3;
  }
  const int cb = (lane >> 3) & 1;

  float acc[4][8][4];
#pragma unroll
  for (int mt = 0; mt < 4; ++mt)
#pragma unroll
    for (int n8 = 0; n8 < 8; ++n8)
#pragma unroll
      for (int j = 0; j < 4; ++j) acc[mt][n8][j] = 0.f;

  float4 av[4];

#pragma unroll
  for (int i = 0; i < 4; ++i) {
    const int col = aseg + i * 4;
    av[i] = (col < I) ? *reinterpret_cast<const float4*>(xrow + col)
                      : make_float4(0.f, 0.f, 0.f, 0.f);
  }
  {
    const unsigned char* src = g_wB;
    const unsigned char* srcL = g_wB + (size_t)NCH * WIMG;
#pragma unroll
    for (int i = 0; i < 4; ++i) {
      CPASYNC16(sb + GB_HI + tid * 16 + i * 4096, src + tid * 16 + i * 4096);
      CPASYNC16(sb + GB_LO + tid * 16 + i * 4096, srcL + tid * 16 + i * 4096);
    }
    asm volatile("cp.async.commit_group;" ::: "memory");
  }
  {
#pragma unroll
    for (int half = 0; half < 2; ++half) {
      const float4 p = av[2 * half];
      const float4 q = av[2 * half + 1];
      const float fs[8] = {p.x, p.y, p.z, p.w, q.x, q.y, q.z, q.w};
      uint32_t hu[4], lu[4];
#pragma unroll
      for (int jj = 0; jj < 4; ++jj) {
        __nv_bfloat16 h0 = __float2bfloat16(fs[2 * jj]);
        __nv_bfloat16 h1 = __float2bfloat16(fs[2 * jj + 1]);
        __nv_bfloat16 l0 = __float2bfloat16(fs[2 * jj] - __bfloat162float(h0));
        __nv_bfloat16 l1 = __float2bfloat16(fs[2 * jj + 1] - __bfloat162float(h1));
        hu[jj] = (uint32_t)__bfloat16_as_ushort(h0) |
                 ((uint32_t)__bfloat16_as_ushort(h1) << 16);
        lu[jj] = (uint32_t)__bfloat16_as_ushort(l0) |
                 ((uint32_t)__bfloat16_as_ushort(l1) << 16);
      }
      const int cc = (aseg >> 3) + half;
      const uint32_t off = aDstBase + ((uint32_t)(cc ^ aXor) << 4);
      *reinterpret_cast<uint4*>(smem + GA_HI + off) = make_uint4(hu[0], hu[1], hu[2], hu[3]);
      *reinterpret_cast<uint4*>(smem + GA_LO + off) = make_uint4(lu[0], lu[1], lu[2], lu[3]);
    }
  }

  for (int c = 0; c < NCH; ++c) {
    asm volatile("cp.async.wait_group 0;" ::: "memory");
    __syncthreads();

    const int nc = c + 1;
    if (nc < NCH) {
      const uint32_t nst = sb + (nc & 1) * GSTAGE;
      const unsigned char* src = g_wB + (size_t)nc * WIMG;
      const unsigned char* srcL = g_wB + (size_t)(NCH + nc) * WIMG;
#pragma unroll
      for (int i = 0; i < 4; ++i) {
        CPASYNC16(nst + GB_HI + tid * 16 + i * 4096, src + tid * 16 + i * 4096);
        CPASYNC16(nst + GB_LO + tid * 16 + i * 4096, srcL + tid * 16 + i * 4096);
      }
      asm volatile("cp.async.commit_group;" ::: "memory");
      const int colbase = nc * 32 + aseg;
#pragma unroll
      for (int i = 0; i < 4; ++i) {
        const int col = colbase + i * 4;
        av[i] = (col < I) ? *reinterpret_cast<const float4*>(xrow + col)
                          : make_float4(0.f, 0.f, 0.f, 0.f);
      }
    }

    const uint32_t st = sb + (c & 1) * GSTAGE;
#pragma unroll
    for (int k16 = 0; k16 < 2; ++k16) {
      uint32_t ah[4][4], al[4][4], bb[4][4];
      const int kca = k16 * 2 + ca;
      const int kcb = k16 * 2 + cb;
#pragma unroll
      for (int mt = 0; mt < 4; ++mt)
        LDSM4(ah[mt], st + GA_HI + raddr[mt] + (((kca ^ sxa[mt])) << 4));
#pragma unroll
      for (int g = 0; g < 4; ++g)
        LDSM4(bb[g], st + GB_HI + rbad[g] + (((kcb ^ sxb[g])) << 4));
#pragma unroll
      for (int mt = 0; mt < 4; ++mt)
#pragma unroll
        for (int g = 0; g < 4; ++g) {
          MMA16816(acc[mt][2 * g], ah[mt], bb[g][0], bb[g][1]);
          MMA16816(acc[mt][2 * g + 1], ah[mt], bb[g][2], bb[g][3]);
        }
#pragma unroll
      for (int mt = 0; mt < 4; ++mt)
        LDSM4(al[mt], st + GA_LO + raddr[mt] + (((kca ^ sxa[mt])) << 4));
#pragma unroll
      for (int mt = 0; mt < 4; ++mt)
#pragma unroll
        for (int g = 0; g < 4; ++g) {
          MMA16816(acc[mt][2 * g], al[mt], bb[g][0], bb[g][1]);
          MMA16816(acc[mt][2 * g + 1], al[mt], bb[g][2], bb[g][3]);
        }
#pragma unroll
      for (int g = 0; g < 4; ++g)
        LDSM4(bb[g], st + GB_LO + rbad[g] + (((kcb ^ sxb[g])) << 4));
#pragma unroll
      for (int mt = 0; mt < 4; ++mt)
#pragma unroll
        for (int g = 0; g < 4; ++g) {
          MMA16816(acc[mt][2 * g], ah[mt], bb[g][0], bb[g][1]);
          MMA16816(acc[mt][2 * g + 1], ah[mt], bb[g][2], bb[g][3]);
        }
    }

    if (nc < NCH) {
      unsigned char* stn = smem + (nc & 1) * GSTAGE;
#pragma unroll
      for (int half = 0; half < 2; ++half) {
        uint32_t hu[4], lu[4];
        const float4 p = av[2 * half];
        const float4 q = av[2 * half + 1];
        const float fs[8] = {p.x, p.y, p.z, p.w, q.x, q.y, q.z, q.w};
#pragma unroll
        for (int jj = 0; jj < 4; ++jj) {
          __nv_bfloat16 h0 = __float2bfloat16(fs[2 * jj]);
          __nv_bfloat16 h1 = __float2bfloat16(fs[2 * jj + 1]);
          __nv_bfloat16 l0 = __float2bfloat16(fs[2 * jj] - __bfloat162float(h0));
          __nv_bfloat16 l1 = __float2bfloat16(fs[2 * jj + 1] - __bfloat162float(h1));
          hu[jj] = (uint32_t)__bfloat16_as_ushort(h0) |
                   ((uint32_t)__bfloat16_as_ushort(h1) << 16);
          lu[jj] = (uint32_t)__bfloat16_as_ushort(l0) |
                   ((uint32_t)__bfloat16_as_ushort(l1) << 16);
        }
        const int cc = (aseg >> 3) + half;
        const uint32_t off = aDstBase + ((uint32_t)(cc ^ aXor) << 4);
        *reinterpret_cast<uint4*>(stn + GA_HI + off) = make_uint4(hu[0], hu[1], hu[2], hu[3]);
        *reinterpret_cast<uint4*>(stn + GA_LO + off) = make_uint4(lu[0], lu[1], lu[2], lu[3]);
      }
    }
  }

#pragma unroll
  for (int mt = 0; mt < 4; ++mt) {
    const int r0 = m0 + wm + mt * 16 + (lane >> 2);
#pragma unroll
    for (int n8 = 0; n8 < 8; ++n8) {
      const int col = wn + n8 * 8 + (lane & 3) * 2;
      *reinterpret_cast<float2*>(g_curx + (size_t)r0 * H + col) =
          make_float2(acc[mt][n8][0], acc[mt][n8][1]);
      *reinterpret_cast<float2*>(g_curx + (size_t)(r0 + 8) * H + col) =
          make_float2(acc[mt][n8][2], acc[mt][n8][3]);
    }
  }
}

// ---------------------------------------------------------------------------
// Kernel 2: persistent BRF recurrence with SPARSE spike propagation.
// 64 clusters x 2 CTAs x 256 thr. Thread (hl = tid&127, p = tid>>7) owns
// hidden unit rank*128+hl for batch rows row0+2p, row0+2p+1.
// z exchanged as bitmasks (8 uint32 per row); matmuls are bit-scan loops.
// ---------------------------------------------------------------------------
__global__ void __cluster_dims__(2, 1, 1) __launch_bounds__(256, 1)
rec_kernel(const float* __restrict__ Wh, const float* __restrict__ omp,
           const float* __restrict__ bop, const float* __restrict__ Wo,
           const float* __restrict__ taup, const int* __restrict__ Y,
           float* __restrict__ out) {
  extern __shared__ float sm[];
  uint32_t* zm = reinterpret_cast<uint32_t*>(sm + SM_ZM);  // [2][4][8]
  float* Ws = sm + SM_WS;
  float* WoT = sm + SM_WOT;
  float* pouA = sm + SM_POUA;
  float* pouB = sm + SM_POUB;
  float* ous = sm + SM_OUS;
  float* alph = sm + SM_AL;

  const int tid = threadIdx.x;
  const int lane = tid & 31;
  unsigned rank;
  asm("mov.u32 %0, %%cluster_ctarank;" : "=r"(rank));
  const int cl = blockIdx.x >> 1, row0 = cl * 4;
  const int hl = tid & 127, p = tid >> 7;

  // ---- init smem ----
  for (int i = tid; i < 32768; i += 256) {
    int j = i >> 7, hh = i & 127;
    Ws[i] = Wh[(size_t)((int)rank * 128 + hh) * WHS + I + j];
  }
  for (int i = tid; i < 2560; i += 256) {
    int hh = i / 20, o = i - hh * 20;
    WoT[i] = Wo[o * H + (int)rank * 128 + hh];
  }
  if (tid < O) alph[tid] = expf(-DELTA / taup[tid]);
  if (tid < 64) zm[tid] = 0u;
  for (int i = tid; i < 160; i += 256) { pouA[i] = 0.f; pouB[i] = 0.f; }
  if (tid < 80) ous[tid] = 0.f;

  const int hg = (int)rank * 128 + hl;
  const float om = fabsf(omp[hg]);
  const float dm = DELTA * om;
  const float pom = (-1.f + sqrtf(1.f - dm * dm)) / DELTA;
  const float bof = fabsf(bop[hg]);
  float u[2] = {0, 0}, v[2] = {0, 0}, q[2] = {0, 0}, zr[2] = {0, 0};
  float lossacc = 0.f;
  int yprev = 0;

  const unsigned zrem = mapa_rank(smem_u32(zm), rank ^ 1u);
  const unsigned prem = mapa_rank(smem_u32(pouB), 0u);
  const int jword = (int)rank * 4 + ((tid >> 5) & 3);

  __syncthreads();
  cluster_sync_all();

  for (int t = 0; t < T; ++t) {
    const int cb = t & 1, nb = cb ^ 1;

    // ---- readout of step t-1 (rank0, threads 0-3) ----
    if (rank == 0 && tid < 4) {
      int ynew = Y[t * B + row0 + tid];
      if (t > 0) {
        const int pb = cb ^ 1;
        const float* pa = pouA + pb * 80 + tid * 20;
        const float* pbp = pouB + pb * 80 + tid * 20;
        float m = -1e30f, ly = 0.f;
        for (int o = 0; o < O; ++o) {
          float a = alph[o];
          float s = ous[tid * 20 + o] * a + (1.f - a) * (pa[o] + pbp[o]);
          ous[tid * 20 + o] = s;
          out[(size_t)(t - 1) * B * O + (size_t)(row0 + tid) * O + o] = s;
          m = fmaxf(m, s);
          if (o == yprev) ly = s;
        }
        float se = 0.f;
        for (int o = 0; o < O; ++o) se += expf(ous[tid * 20 + o] - m);
        lossacc += -(ly - m - logf(se)) * (1.f / (float)B);
      }
      yprev = ynew;
    }

    // ---- input current for this thread's 2 rows ----
    const float* cp = g_curx + ((size_t)t * B + row0 + 2 * p) * H + hg;
    float a0 = cp[0], a1 = cp[H];

    // ---- sparse z_{t-1} @ W_z^T ----
    {
      const uint32_t* mr0 = zm + (cb * 4 + 2 * p) * 8;
      const uint32_t* mr1 = zm + (cb * 4 + 2 * p + 1) * 8;
#pragma unroll
      for (int w8 = 0; w8 < 8; ++w8) {
        uint32_t m = mr0[w8];
        while (m) {
          int bp = __ffs(m) - 1;
          m &= m - 1;
          a0 += Ws[((w8 << 5) + bp) * 128 + hl];
        }
      }
#pragma unroll
      for (int w8 = 0; w8 < 8; ++w8) {
        uint32_t m = mr1[w8];
        while (m) {
          int bp = __ffs(m) - 1;
          m &= m - 1;
          a1 += Ws[((w8 << 5) + bp) * 128 + hl];
        }
      }
    }

    // ---- state update + spike ----
    const float cw[2] = {a0, a1};
#pragma unroll
    for (int rr = 0; rr < 2; ++rr) {
      float b = pom - bof - q[rr];
      float un = u[rr] + DELTA * (b * u[rr] - om * v[rr] + cw[rr]);
      float vn = v[rr] + DELTA * (om * un + b * v[rr]);
      float z = (un - THETA - q[rr]) > 0.f ? 1.f : 0.f;
      q[rr] = GAMMA * q[rr] + z;
      u[rr] = un; v[rr] = vn; zr[rr] = z;
    }

    // ---- build + exchange spike bitmasks ----
    const unsigned mk0 = __ballot_sync(0xffffffffu, zr[0] > 0.f);
    const unsigned mk1 = __ballot_sync(0xffffffffu, zr[1] > 0.f);
    if (lane == 0) {
      const int i0 = (nb * 4 + 2 * p) * 8 + jword;
      const int i1 = (nb * 4 + 2 * p + 1) * 8 + jword;
      zm[i0] = mk0; zm[i1] = mk1;
      stc_u32(zrem + (unsigned)i0 * 4u, mk0);
      stc_u32(zrem + (unsigned)i1 * 4u, mk1);
    }
    __syncthreads();

    // ---- sparse readout partials over this CTA's h-half ----
    if (tid < 80) {
      const int r = tid / 20, o = tid - r * 20;
      float s = 0.f;
      const uint32_t* mw = zm + (nb * 4 + r) * 8 + (int)rank * 4;
#pragma unroll
      for (int w = 0; w < 4; ++w) {
        uint32_t m = mw[w];
        while (m) {
          int bp = __ffs(m) - 1;
          m &= m - 1;
          s += WoT[((w << 5) + bp) * 20 + o];
        }
      }
      if (rank == 0) pouA[cb * 80 + tid] = s;
      else stc_f32(prem + (unsigned)(cb * 80 + tid) * 4u, s);
    }

    cluster_sync_all();
  }

  // ---- final readout (t = T-1) ----
  if (rank == 0 && tid < 4) {
    const int pb = (T - 1) & 1;
    const float* pa = pouA + pb * 80 + tid * 20;
    const float* pbp = pouB + pb * 80 + tid * 20;
    float m = -1e30f, ly = 0.f;
    for (int o = 0; o < O; ++o) {
      float a = alph[o];
      float s = ous[tid * 20 + o] * a + (1.f - a) * (pa[o] + pbp[o]);
      ous[tid * 20 + o] = s;
      out[(size_t)(T - 1) * B * O + (size_t)(row0 + tid) * O + o] = s;
      m = fmaxf(m, s);
      if (o == yprev) ly = s;
    }
    float se = 0.f;
    for (int o = 0; o < O; ++o) se += expf(ous[tid * 20 + o] - m);
    lossacc += -(ly - m - logf(se)) * (1.f / (float)B);
    g_loss[row0 + tid] = lossacc;
  }
  __syncthreads();

#pragma unroll
  for (int rr = 0; rr < 2; ++rr) {
    size_t idx = (size_t)(row0 + 2 * p + rr) * H + hg;
    out[OFF_ZF + idx] = zr[rr];
    out[OFF_UF + idx] = u[rr];
  }
  if (rank == 0 && tid < 80) {
    int rr = tid / 20, o = tid - rr * 20;
    out[OFF_OUF + (size_t)(row0 + rr) * O + o] = ous[tid];
  }
}

// ---------------------------------------------------------------------------
// Kernel 3: deterministic loss reduction
// ---------------------------------------------------------------------------
__global__ void loss_sum_kernel(float* __restrict__ out) {
  __shared__ float s[256];
  s[threadIdx.x] = g_loss[threadIdx.x];
  __syncthreads();
  for (int st = 128; st > 0; st >>= 1) {
    if (threadIdx.x < st) s[threadIdx.x] += s[threadIdx.x + st];
    __syncthreads();
  }
  if (threadIdx.x == 0) out[OFF_LOSS] = s[0];
}

// ---------------------------------------------------------------------------
extern "C" void kernel_launch(void* const* d_in, const int* in_sizes, int n_in,
                              void* d_out, int out_size) {
  const float* x = (const float*)d_in[0];
  const int* y = (const int*)d_in[1];
  const float* Wh = (const float*)d_in[2];
  const float* omega = (const float*)d_in[3];
  const float* boff = (const float*)d_in[4];
  const float* Wo = (const float*)d_in[5];
  const float* tau = (const float*)d_in[6];
  float* out = (float*)d_out;

  cudaFuncSetAttribute(gemm_mma_kernel, cudaFuncAttributeMaxDynamicSharedMemorySize,
                       GS_TOTAL);
  cudaFuncSetAttribute(rec_kernel, cudaFuncAttributeMaxDynamicSharedMemorySize,
                       SM_TOT * (int)sizeof(float));

  prep_w_kernel<<<2 * NCH, 256>>>(Wh);
  gemm_mma_kernel<<<(T * B) / 128, 256, GS_TOTAL>>>(x);
  rec_kernel<<<B / 2, 256, SM_TOT * sizeof(float)>>>(Wh, omega, boff, Wo, tau, y, out);
  loss_sum_kernel<<<1, 256>>>(out);
}

// round 8
// speedup vs baseline: 2.2637x; 1.2644x over previous
#include <cuda_runtime.h>
#include <cuda_fp16.h>
#include <cstdint>
#include <cstddef>

namespace {
constexpr int T = 1000, B = 256, I = 700, H = 256, O = 20, WHS = I + H;
constexpr float DELTA = 0.01f, GAMMA = 0.9f, THETA = 1.0f;
constexpr size_t OFF_LOSS = (size_t)T * B * O;
constexpr size_t OFF_ZF = OFF_LOSS + 1;
constexpr size_t OFF_UF = OFF_ZF + (size_t)B * H;
constexpr size_t OFF_OUF = OFF_UF + (size_t)B * H;

// ---- recurrence kernel smem layout (float offsets) ----
constexpr int SM_ZM = 0;                    // [2][4][8] uint32 spike bitmasks
constexpr int SM_WS = 64;                   // [256][128] W_z half: [j][h_local]
constexpr int SM_WOT = SM_WS + 32768;       // [128][20] W_o half
constexpr int SM_POUA = SM_WOT + 2560;      // [2][80]
constexpr int SM_POUB = SM_POUA + 160;      // [2][80]
constexpr int SM_OUS = SM_POUB + 160;       // [4][20]
constexpr int SM_AL = SM_OUS + 80;          // [20]
constexpr int SM_TOT = SM_AL + 32;

// ---- mma.sync GEMM config: single-term fp16, 128x256 CTA, x read once ----
constexpr int NCH = 22;                 // K chunks of 32 (K padded to 704)
constexpr int WIMG = 256 * 64;          // 16 KB: one chunk's W image (fp16)
constexpr int GA = 0;                   // A: [128 rows][64B] swizzled (8 KB)
constexpr int GB = 8192;                // B: [256 rows][64B] swizzled (16 KB)
constexpr int GSTAGE = 24576;
constexpr int GS_TOTAL = 2 * GSTAGE;    // 48 KB
}  // namespace

__device__ float g_curx[(size_t)T * B * H];  // x @ W_x^T
__device__ float g_loss[B];
__device__ __align__(128) unsigned char g_wB[NCH * WIMG];  // per-chunk W images

// ---------------------------------------------------------------------------
// helpers
// ---------------------------------------------------------------------------
__device__ __forceinline__ unsigned smem_u32(const void* p) {
  return (unsigned)__cvta_generic_to_shared(p);
}
__device__ __forceinline__ void cluster_sync_all() {
  asm volatile("barrier.cluster.arrive.aligned;" ::: "memory");
  asm volatile("barrier.cluster.wait.aligned;" ::: "memory");
}
__device__ __forceinline__ unsigned mapa_rank(unsigned a, unsigned r) {
  unsigned o;
  asm("mapa.shared::cluster.u32 %0, %1, %2;" : "=r"(o) : "r"(a), "r"(r));
  return o;
}
__device__ __forceinline__ void stc_f32(unsigned a, float v) {
  asm volatile("st.shared::cluster.f32 [%0], %1;" :: "r"(a), "f"(v) : "memory");
}
__device__ __forceinline__ void stc_u32(unsigned a, unsigned v) {
  asm volatile("st.shared::cluster.u32 [%0], %1;" :: "r"(a), "r"(v) : "memory");
}
__device__ __forceinline__ uint32_t pack_half2(float a, float b) {
  __half2 h = __floats2half2_rn(a, b);
  return *reinterpret_cast<uint32_t*>(&h);
}

#define LDSM4(r, addr)                                                        \
  asm volatile("ldmatrix.sync.aligned.m8n8.x4.shared.b16 {%0,%1,%2,%3}, [%4];" \
               : "=r"((r)[0]), "=r"((r)[1]), "=r"((r)[2]), "=r"((r)[3])        \
               : "r"(addr))

#define MMA16816F(d, a, b0, b1)                                               \
  asm volatile(                                                               \
      "mma.sync.aligned.m16n8k16.row.col.f32.f16.f16.f32 "                    \
      "{%0,%1,%2,%3},{%4,%5,%6,%7},{%8,%9},{%0,%1,%2,%3};"                    \
      : "+f"((d)[0]), "+f"((d)[1]), "+f"((d)[2]), "+f"((d)[3])                \
      : "r"((a)[0]), "r"((a)[1]), "r"((a)[2]), "r"((a)[3]), "r"(b0), "r"(b1))

#define CPASYNC16(dst, src)                                                   \
  asm volatile("cp.async.cg.shared.global [%0], [%1], 16;" :: "r"(dst),       \
               "l"(src) : "memory")

// ---------------------------------------------------------------------------
// Kernel 0: W_h[:, :700] -> fp16, pre-swizzled smem-image layout.
// image[n][cSw][8 fp16], cSw = c ^ ((n>>1)&3). One block per chunk.
// ---------------------------------------------------------------------------
__global__ void prep_w_kernel(const float* __restrict__ Wh) {
  const int chunk = blockIdx.x;
  const int n = threadIdx.x;  // 0..255
  unsigned char* dst = g_wB + (size_t)chunk * WIMG + n * 64;
#pragma unroll
  for (int c = 0; c < 4; ++c) {
    uint32_t u[4];
#pragma unroll
    for (int jj = 0; jj < 4; ++jj) {
      const int k = chunk * 32 + c * 8 + jj * 2;
      float w0 = (k < I) ? Wh[(size_t)n * WHS + k] : 0.f;
      float w1 = (k + 1 < I) ? Wh[(size_t)n * WHS + k + 1] : 0.f;
      u[jj] = pack_half2(w0, w1);
    }
    const int cSw = c ^ ((n >> 1) & 3);
    *reinterpret_cast<uint4*>(dst + cSw * 16) = make_uint4(u[0], u[1], u[2], u[3]);
  }
}

// ---------------------------------------------------------------------------
// Kernel 1: cur_x = x @ W_x^T via mma.sync fp16 (single term).
// CTA: 128(M) x 256(N), 8 warps (2m x 4n), warp tile 64x64.
// ---------------------------------------------------------------------------
__global__ __launch_bounds__(256, 1) void gemm_mma_kernel(const float* __restrict__ X) {
  extern __shared__ __align__(1024) unsigned char smem[];
  const uint32_t sb = smem_u32(smem);
  const int tid = threadIdx.x;
  const int lane = tid & 31, wid = tid >> 5;
  const int wm = (wid & 1) * 64, wn = (wid >> 1) * 64;
  const int m0 = blockIdx.x * 128;

  const int arow = tid >> 1;
  const int aseg = (tid & 1) << 4;
  const float* xrow = X + (size_t)(m0 + arow) * I;
  const uint32_t aXor = ((arow >> 1) & 3);
  const uint32_t aDst = (uint32_t)(arow * 64);

  int raddr[4], sxa[4], rbad[4], sxb[4];
#pragma unroll
  for (int mt = 0; mt < 4; ++mt) {
    int r = wm + mt * 16 + (lane & 15);
    raddr[mt] = r * 64;
    sxa[mt] = (r >> 1) & 3;
  }
  const int ca = lane >> 4;
#pragma unroll
  for (int g = 0; g < 4; ++g) {
    int n = wn + g * 16 + (lane & 7) + ((lane >> 4) << 3);
    rbad[g] = n * 64;
    sxb[g] = (n >> 1) & 3;
  }
  const int cb = (lane >> 3) & 1;

  float acc[4][8][4];
#pragma unroll
  for (int mt = 0; mt < 4; ++mt)
#pragma unroll
    for (int n8 = 0; n8 < 8; ++n8)
#pragma unroll
      for (int j = 0; j < 4; ++j) acc[mt][n8][j] = 0.f;

  float4 av[4];

  // ---- prologue: chunk 0 ----
#pragma unroll
  for (int i = 0; i < 4; ++i) {
    const int col = aseg + i * 4;
    av[i] = (col < I) ? *reinterpret_cast<const float4*>(xrow + col)
                      : make_float4(0.f, 0.f, 0.f, 0.f);
  }
  {
#pragma unroll
    for (int i = 0; i < 4; ++i)
      CPASYNC16(sb + GB + tid * 16 + i * 4096, g_wB + tid * 16 + i * 4096);
    asm volatile("cp.async.commit_group;" ::: "memory");
  }
  {
#pragma unroll
    for (int half = 0; half < 2; ++half) {
      const float4 p = av[2 * half];
      const float4 q = av[2 * half + 1];
      uint32_t hu[4];
      hu[0] = pack_half2(p.x, p.y);
      hu[1] = pack_half2(p.z, p.w);
      hu[2] = pack_half2(q.x, q.y);
      hu[3] = pack_half2(q.z, q.w);
      const int cc = (aseg >> 3) + half;
      const uint32_t off = aDst + ((uint32_t)(cc ^ aXor) << 4);
      *reinterpret_cast<uint4*>(smem + GA + off) = make_uint4(hu[0], hu[1], hu[2], hu[3]);
    }
  }

  // ---- main loop ----
  for (int c = 0; c < NCH; ++c) {
    asm volatile("cp.async.wait_group 0;" ::: "memory");
    __syncthreads();

    const int nc = c + 1;
    if (nc < NCH) {
      const uint32_t nst = sb + (nc & 1) * GSTAGE;
      const unsigned char* src = g_wB + (size_t)nc * WIMG;
#pragma unroll
      for (int i = 0; i < 4; ++i)
        CPASYNC16(nst + GB + tid * 16 + i * 4096, src + tid * 16 + i * 4096);
      asm volatile("cp.async.commit_group;" ::: "memory");
      const int colbase = nc * 32 + aseg;
#pragma unroll
      for (int i = 0; i < 4; ++i) {
        const int col = colbase + i * 4;
        av[i] = (col < I) ? *reinterpret_cast<const float4*>(xrow + col)
                          : make_float4(0.f, 0.f, 0.f, 0.f);
      }
    }

    const uint32_t st = sb + (c & 1) * GSTAGE;
#pragma unroll
    for (int k16 = 0; k16 < 2; ++k16) {
      uint32_t ah[4][4], bb[4][4];
      const int kca = k16 * 2 + ca;
      const int kcb = k16 * 2 + cb;
#pragma unroll
      for (int mt = 0; mt < 4; ++mt)
        LDSM4(ah[mt], st + GA + raddr[mt] + (((kca ^ sxa[mt])) << 4));
#pragma unroll
      for (int g = 0; g < 4; ++g)
        LDSM4(bb[g], st + GB + rbad[g] + (((kcb ^ sxb[g])) << 4));
#pragma unroll
      for (int mt = 0; mt < 4; ++mt)
#pragma unroll
        for (int g = 0; g < 4; ++g) {
          MMA16816F(acc[mt][2 * g], ah[mt], bb[g][0], bb[g][1]);
          MMA16816F(acc[mt][2 * g + 1], ah[mt], bb[g][2], bb[g][3]);
        }
    }

    if (nc < NCH) {
      unsigned char* stn = smem + (nc & 1) * GSTAGE;
#pragma unroll
      for (int half = 0; half < 2; ++half) {
        const float4 p = av[2 * half];
        const float4 q = av[2 * half + 1];
        uint32_t hu[4];
        hu[0] = pack_half2(p.x, p.y);
        hu[1] = pack_half2(p.z, p.w);
        hu[2] = pack_half2(q.x, q.y);
        hu[3] = pack_half2(q.z, q.w);
        const int cc = (aseg >> 3) + half;
        const uint32_t off = aDst + ((uint32_t)(cc ^ aXor) << 4);
        *reinterpret_cast<uint4*>(stn + GA + off) = make_uint4(hu[0], hu[1], hu[2], hu[3]);
      }
    }
  }

  // ---- epilogue: acc -> g_curx ----
#pragma unroll
  for (int mt = 0; mt < 4; ++mt) {
    const int r0 = m0 + wm + mt * 16 + (lane >> 2);
#pragma unroll
    for (int n8 = 0; n8 < 8; ++n8) {
      const int col = wn + n8 * 8 + (lane & 3) * 2;
      *reinterpret_cast<float2*>(g_curx + (size_t)r0 * H + col) =
          make_float2(acc[mt][n8][0], acc[mt][n8][1]);
      *reinterpret_cast<float2*>(g_curx + (size_t)(r0 + 8) * H + col) =
          make_float2(acc[mt][n8][2], acc[mt][n8][3]);
    }
  }
}

// ---------------------------------------------------------------------------
// Kernel 2: persistent BRF recurrence, sparse spike propagation + cur prefetch.
// 64 clusters x 2 CTAs x 256 thr.
// ---------------------------------------------------------------------------
__global__ void __cluster_dims__(2, 1, 1) __launch_bounds__(256, 1)
rec_kernel(const float* __restrict__ Wh, const float* __restrict__ omp,
           const float* __restrict__ bop, const float* __restrict__ Wo,
           const float* __restrict__ taup, const int* __restrict__ Y,
           float* __restrict__ out) {
  extern __shared__ float sm[];
  uint32_t* zm = reinterpret_cast<uint32_t*>(sm + SM_ZM);  // [2][4][8]
  float* Ws = sm + SM_WS;
  float* WoT = sm + SM_WOT;
  float* pouA = sm + SM_POUA;
  float* pouB = sm + SM_POUB;
  float* ous = sm + SM_OUS;
  float* alph = sm + SM_AL;

  const int tid = threadIdx.x;
  const int lane = tid & 31;
  unsigned rank;
  asm("mov.u32 %0, %%cluster_ctarank;" : "=r"(rank));
  const int cl = blockIdx.x >> 1, row0 = cl * 4;
  const int hl = tid & 127, p = tid >> 7;

  for (int i = tid; i < 32768; i += 256) {
    int j = i >> 7, hh = i & 127;
    Ws[i] = Wh[(size_t)((int)rank * 128 + hh) * WHS + I + j];
  }
  for (int i = tid; i < 2560; i += 256) {
    int hh = i / 20, o = i - hh * 20;
    WoT[i] = Wo[o * H + (int)rank * 128 + hh];
  }
  if (tid < O) alph[tid] = expf(-DELTA / taup[tid]);
  if (tid < 64) zm[tid] = 0u;
  for (int i = tid; i < 160; i += 256) { pouA[i] = 0.f; pouB[i] = 0.f; }
  if (tid < 80) ous[tid] = 0.f;

  const int hg = (int)rank * 128 + hl;
  const float om = fabsf(omp[hg]);
  const float dm = DELTA * om;
  const float pom = (-1.f + sqrtf(1.f - dm * dm)) / DELTA;
  const float bof = fabsf(bop[hg]);
  float u[2] = {0, 0}, v[2] = {0, 0}, q[2] = {0, 0}, zr[2] = {0, 0};
  float lossacc = 0.f;
  int yprev = 0;

  const unsigned zrem = mapa_rank(smem_u32(zm), rank ^ 1u);
  const unsigned prem = mapa_rank(smem_u32(pouB), 0u);
  const int jword = (int)rank * 4 + ((tid >> 5) & 3);

  // prefetch cur for t=0
  const float* cp0 = g_curx + ((size_t)row0 + 2 * p) * H + hg;
  float c0 = cp0[0], c1 = cp0[H];

  __syncthreads();
  cluster_sync_all();

  for (int t = 0; t < T; ++t) {
    const int cb = t & 1, nb = cb ^ 1;

    // issue next step's cur loads early (hidden behind this step's work)
    float c0n = 0.f, c1n = 0.f;
    if (t + 1 < T) {
      const float* cpn = g_curx + ((size_t)(t + 1) * B + row0 + 2 * p) * H + hg;
      c0n = cpn[0]; c1n = cpn[H];
    }

    // ---- readout of step t-1 (rank0, threads 0-3) ----
    if (rank == 0 && tid < 4) {
      int ynew = Y[t * B + row0 + tid];
      if (t > 0) {
        const int pb = cb ^ 1;
        const float* pa = pouA + pb * 80 + tid * 20;
        const float* pbp = pouB + pb * 80 + tid * 20;
        float m = -1e30f, ly = 0.f;
        for (int o = 0; o < O; ++o) {
          float a = alph[o];
          float s = ous[tid * 20 + o] * a + (1.f - a) * (pa[o] + pbp[o]);
          ous[tid * 20 + o] = s;
          out[(size_t)(t - 1) * B * O + (size_t)(row0 + tid) * O + o] = s;
          m = fmaxf(m, s);
          if (o == yprev) ly = s;
        }
        float se = 0.f;
        for (int o = 0; o < O; ++o) se += expf(ous[tid * 20 + o] - m);
        lossacc += -(ly - m - logf(se)) * (1.f / (float)B);
      }
      yprev = ynew;
    }

    float a0 = c0, a1 = c1;

    // ---- sparse z_{t-1} @ W_z^T ----
    {
      const uint32_t* mr0 = zm + (cb * 4 + 2 * p) * 8;
      const uint32_t* mr1 = zm + (cb * 4 + 2 * p + 1) * 8;
#pragma unroll
      for (int w8 = 0; w8 < 8; ++w8) {
        uint32_t m = mr0[w8];
        while (m) {
          int bp = __ffs(m) - 1;
          m &= m - 1;
          a0 += Ws[((w8 << 5) + bp) * 128 + hl];
        }
      }
#pragma unroll
      for (int w8 = 0; w8 < 8; ++w8) {
        uint32_t m = mr1[w8];
        while (m) {
          int bp = __ffs(m) - 1;
          m &= m - 1;
          a1 += Ws[((w8 << 5) + bp) * 128 + hl];
        }
      }
    }

    // ---- state update + spike ----
    const float cw[2] = {a0, a1};
#pragma unroll
    for (int rr = 0; rr < 2; ++rr) {
      float b = pom - bof - q[rr];
      float un = u[rr] + DELTA * (b * u[rr] - om * v[rr] + cw[rr]);
      float vn = v[rr] + DELTA * (om * un + b * v[rr]);
      float z = (un - THETA - q[rr]) > 0.f ? 1.f : 0.f;
      q[rr] = GAMMA * q[rr] + z;
      u[rr] = un; v[rr] = vn; zr[rr] = z;
    }

    // ---- build + exchange spike bitmasks ----
    const unsigned mk0 = __ballot_sync(0xffffffffu, zr[0] > 0.f);
    const unsigned mk1 = __ballot_sync(0xffffffffu, zr[1] > 0.f);
    if (lane == 0) {
      const int i0 = (nb * 4 + 2 * p) * 8 + jword;
      const int i1 = (nb * 4 + 2 * p + 1) * 8 + jword;
      zm[i0] = mk0; zm[i1] = mk1;
      stc_u32(zrem + (unsigned)i0 * 4u, mk0);
      stc_u32(zrem + (unsigned)i1 * 4u, mk1);
    }
    __syncthreads();

    // ---- sparse readout partials over this CTA's h-half ----
    if (tid < 80) {
      const int r = tid / 20, o = tid - r * 20;
      float s = 0.f;
      const uint32_t* mw = zm + (nb * 4 + r) * 8 + (int)rank * 4;
#pragma unroll
      for (int w = 0; w < 4; ++w) {
        uint32_t m = mw[w];
        while (m) {
          int bp = __ffs(m) - 1;
          m &= m - 1;
          s += WoT[((w << 5) + bp) * 20 + o];
        }
      }
      if (rank == 0) pouA[cb * 80 + tid] = s;
      else stc_f32(prem + (unsigned)(cb * 80 + tid) * 4u, s);
    }

    cluster_sync_all();
    c0 = c0n; c1 = c1n;
  }

  // ---- final readout (t = T-1) ----
  if (rank == 0 && tid < 4) {
    const int pb = (T - 1) & 1;
    const float* pa = pouA + pb * 80 + tid * 20;
    const float* pbp = pouB + pb * 80 + tid * 20;
    float m = -1e30f, ly = 0.f;
    for (int o = 0; o < O; ++o) {
      float a = alph[o];
      float s = ous[tid * 20 + o] * a + (1.f - a) * (pa[o] + pbp[o]);
      ous[tid * 20 + o] = s;
      out[(size_t)(T - 1) * B * O + (size_t)(row0 + tid) * O + o] = s;
      m = fmaxf(m, s);
      if (o == yprev) ly = s;
    }
    float se = 0.f;
    for (int o = 0; o < O; ++o) se += expf(ous[tid * 20 + o] - m);
    lossacc += -(ly - m - logf(se)) * (1.f / (float)B);
    g_loss[row0 + tid] = lossacc;
  }
  __syncthreads();

#pragma unroll
  for (int rr = 0; rr < 2; ++rr) {
    size_t idx = (size_t)(row0 + 2 * p + rr) * H + hg;
    out[OFF_ZF + idx] = zr[rr];
    out[OFF_UF + idx] = u[rr];
  }
  if (rank == 0 && tid < 80) {
    int rr = tid / 20, o = tid - rr * 20;
    out[OFF_OUF + (size_t)(row0 + rr) * O + o] = ous[tid];
  }
}

// ---------------------------------------------------------------------------
// Kernel 3: deterministic loss reduction
// ---------------------------------------------------------------------------
__global__ void loss_sum_kernel(float* __restrict__ out) {
  __shared__ float s[256];
  s[threadIdx.x] = g_loss[threadIdx.x];
  __syncthreads();
  for (int st = 128; st > 0; st >>= 1) {
    if (threadIdx.x < st) s[threadIdx.x] += s[threadIdx.x + st];
    __syncthreads();
  }
  if (threadIdx.x == 0) out[OFF_LOSS] = s[0];
}

// ---------------------------------------------------------------------------
extern "C" void kernel_launch(void* const* d_in, const int* in_sizes, int n_in,
                              void* d_out, int out_size) {
  const float* x = (const float*)d_in[0];
  const int* y = (const int*)d_in[1];
  const float* Wh = (const float*)d_in[2];
  const float* omega = (const float*)d_in[3];
  const float* boff = (const float*)d_in[4];
  const float* Wo = (const float*)d_in[5];
  const float* tau = (const float*)d_in[6];
  float* out = (float*)d_out;

  cudaFuncSetAttribute(gemm_mma_kernel, cudaFuncAttributeMaxDynamicSharedMemorySize,
                       GS_TOTAL);
  cudaFuncSetAttribute(rec_kernel, cudaFuncAttributeMaxDynamicSharedMemorySize,
                       SM_TOT * (int)sizeof(float));

  prep_w_kernel<<<NCH, 256>>>(Wh);
  gemm_mma_kernel<<<(T * B) / 128, 256, GS_TOTAL>>>(x);
  rec_kernel<<<B / 2, 256, SM_TOT * sizeof(float)>>>(Wh, omega, boff, Wo, tau, y, out);
  loss_sum_kernel<<<1, 256>>>(out);
}

// round 10
// speedup vs baseline: 3.3849x; 1.4953x over previous
#include <cuda_runtime.h>
#include <cuda_fp16.h>
#include <cstdint>
#include <cstddef>

namespace {
constexpr int T = 1000, B = 256, I = 700, H = 256, O = 20, WHS = I + H;
constexpr float DELTA = 0.01f, GAMMA = 0.9f, THETA = 1.0f;
constexpr size_t OFF_LOSS = (size_t)T * B * O;
constexpr size_t OFF_ZF = OFF_LOSS + 1;
constexpr size_t OFF_UF = OFF_ZF + (size_t)B * H;
constexpr size_t OFF_OUF = OFF_UF + (size_t)B * H;

// ---- mma.sync GEMM config: single-term fp16, 128x256 CTA, x read once ----
constexpr int NCH = 22;                 // K chunks of 32 (K padded to 704)
constexpr int WIMG = 256 * 64;          // 16 KB: one chunk's W image (fp16)
constexpr int GA = 0;                   // A: [128 rows][64B] swizzled (8 KB)
constexpr int GB = 8192;                // B: [256 rows][64B] swizzled (16 KB)
constexpr int GSTAGE = 24576;
constexpr int GS_TOTAL = 2 * GSTAGE;    // 48 KB

// ---- rec kernel smem ----
constexpr int REC_WZ_BYTES = 256 * 256 * 2;        // fp16 W_z [j][h]
constexpr int REC_SMEM = REC_WZ_BYTES + 2 * 2 * 8 * 4 + 64;
}  // namespace

__device__ float g_curx[(size_t)T * B * H];          // x @ W_x^T
__device__ uint32_t g_zmask[(size_t)T * B * 8];      // spike bitmasks per (t,b)
__device__ float g_losspart[(size_t)T * B];          // per-(t,b) loss partials
__device__ __align__(128) unsigned char g_wB[NCH * WIMG];  // per-chunk W images

// ---------------------------------------------------------------------------
// helpers
// ---------------------------------------------------------------------------
__device__ __forceinline__ unsigned smem_u32(const void* p) {
  return (unsigned)__cvta_generic_to_shared(p);
}
__device__ __forceinline__ uint32_t pack_half2(float a, float b) {
  __half2 h = __floats2half2_rn(a, b);
  return *reinterpret_cast<uint32_t*>(&h);
}

#define LDSM4(r, addr)                                                        \
  asm volatile("ldmatrix.sync.aligned.m8n8.x4.shared.b16 {%0,%1,%2,%3}, [%4];" \
               : "=r"((r)[0]), "=r"((r)[1]), "=r"((r)[2]), "=r"((r)[3])        \
               : "r"(addr))

#define MMA16816F(d, a, b0, b1)                                               \
  asm volatile(                                                               \
      "mma.sync.aligned.m16n8k16.row.col.f32.f16.f16.f32 "                    \
      "{%0,%1,%2,%3},{%4,%5,%6,%7},{%8,%9},{%0,%1,%2,%3};"                    \
      : "+f"((d)[0]), "+f"((d)[1]), "+f"((d)[2]), "+f"((d)[3])                \
      : "r"((a)[0]), "r"((a)[1]), "r"((a)[2]), "r"((a)[3]), "r"(b0), "r"(b1))

#define CPASYNC16(dst, src)                                                   \
  asm volatile("cp.async.cg.shared.global [%0], [%1], 16;" :: "r"(dst),       \
               "l"(src) : "memory")

// ---------------------------------------------------------------------------
// Kernel 0: W_h[:, :700] -> fp16, pre-swizzled smem-image layout.
// image[n][cSw][8 fp16], cSw = c ^ ((n>>1)&3). One block per chunk.
// ---------------------------------------------------------------------------
__global__ void prep_w_kernel(const float* __restrict__ Wh) {
  const int chunk = blockIdx.x;
  const int n = threadIdx.x;  // 0..255
  unsigned char* dst = g_wB + (size_t)chunk * WIMG + n * 64;
#pragma unroll
  for (int c = 0; c < 4; ++c) {
    uint32_t u[4];
#pragma unroll
    for (int jj = 0; jj < 4; ++jj) {
      const int k = chunk * 32 + c * 8 + jj * 2;
      float w0 = (k < I) ? Wh[(size_t)n * WHS + k] : 0.f;
      float w1 = (k + 1 < I) ? Wh[(size_t)n * WHS + k + 1] : 0.f;
      u[jj] = pack_half2(w0, w1);
    }
    const int cSw = c ^ ((n >> 1) & 3);
    *reinterpret_cast<uint4*>(dst + cSw * 16) = make_uint4(u[0], u[1], u[2], u[3]);
  }
}

// ---------------------------------------------------------------------------
// Kernel 1: cur_x = x @ W_x^T via mma.sync fp16 (R8 version, passing).
// CTA: 128(M) x 256(N), 8 warps (2m x 4n), warp tile 64x64.
// ---------------------------------------------------------------------------
__global__ __launch_bounds__(256, 1) void gemm_mma_kernel(const float* __restrict__ X) {
  extern __shared__ __align__(1024) unsigned char smem[];
  const uint32_t sb = smem_u32(smem);
  const int tid = threadIdx.x;
  const int lane = tid & 31, wid = tid >> 5;
  const int wm = (wid & 1) * 64, wn = (wid >> 1) * 64;
  const int m0 = blockIdx.x * 128;

  const int arow = tid >> 1;
  const int aseg = (tid & 1) << 4;
  const float* xrow = X + (size_t)(m0 + arow) * I;
  const uint32_t aXor = ((arow >> 1) & 3);
  const uint32_t aDst = (uint32_t)(arow * 64);

  int raddr[4], sxa[4], rbad[4], sxb[4];
#pragma unroll
  for (int mt = 0; mt < 4; ++mt) {
    int r = wm + mt * 16 + (lane & 15);
    raddr[mt] = r * 64;
    sxa[mt] = (r >> 1) & 3;
  }
  const int ca = lane >> 4;
#pragma unroll
  for (int g = 0; g < 4; ++g) {
    int n = wn + g * 16 + (lane & 7) + ((lane >> 4) << 3);
    rbad[g] = n * 64;
    sxb[g] = (n >> 1) & 3;
  }
  const int cb = (lane >> 3) & 1;

  float acc[4][8][4];
#pragma unroll
  for (int mt = 0; mt < 4; ++mt)
#pragma unroll
    for (int n8 = 0; n8 < 8; ++n8)
#pragma unroll
      for (int j = 0; j < 4; ++j) acc[mt][n8][j] = 0.f;

  float4 av[4];

  // ---- prologue: chunk 0 ----
#pragma unroll
  for (int i = 0; i < 4; ++i) {
    const int col = aseg + i * 4;
    av[i] = (col < I) ? *reinterpret_cast<const float4*>(xrow + col)
                      : make_float4(0.f, 0.f, 0.f, 0.f);
  }
  {
#pragma unroll
    for (int i = 0; i < 4; ++i)
      CPASYNC16(sb + GB + tid * 16 + i * 4096, g_wB + tid * 16 + i * 4096);
    asm volatile("cp.async.commit_group;" ::: "memory");
  }
  {
#pragma unroll
    for (int half = 0; half < 2; ++half) {
      const float4 p = av[2 * half];
      const float4 q = av[2 * half + 1];
      uint32_t hu[4];
      hu[0] = pack_half2(p.x, p.y);
      hu[1] = pack_half2(p.z, p.w);
      hu[2] = pack_half2(q.x, q.y);
      hu[3] = pack_half2(q.z, q.w);
      const int cc = (aseg >> 3) + half;
      const uint32_t off = aDst + ((uint32_t)(cc ^ aXor) << 4);
      *reinterpret_cast<uint4*>(smem + GA + off) = make_uint4(hu[0], hu[1], hu[2], hu[3]);
    }
  }

  // ---- main loop ----
  for (int c = 0; c < NCH; ++c) {
    asm volatile("cp.async.wait_group 0;" ::: "memory");
    __syncthreads();

    const int nc = c + 1;
    if (nc < NCH) {
      const uint32_t nst = sb + (nc & 1) * GSTAGE;
      const unsigned char* src = g_wB + (size_t)nc * WIMG;
#pragma unroll
      for (int i = 0; i < 4; ++i)
        CPASYNC16(nst + GB + tid * 16 + i * 4096, src + tid * 16 + i * 4096);
      asm volatile("cp.async.commit_group;" ::: "memory");
      const int colbase = nc * 32 + aseg;
#pragma unroll
      for (int i = 0; i < 4; ++i) {
        const int col = colbase + i * 4;
        av[i] = (col < I) ? *reinterpret_cast<const float4*>(xrow + col)
                          : make_float4(0.f, 0.f, 0.f, 0.f);
      }
    }

    const uint32_t st = sb + (c & 1) * GSTAGE;
#pragma unroll
    for (int k16 = 0; k16 < 2; ++k16) {
      uint32_t ah[4][4], bb[4][4];
      const int kca = k16 * 2 + ca;
      const int kcb = k16 * 2 + cb;
#pragma unroll
      for (int mt = 0; mt < 4; ++mt)
        LDSM4(ah[mt], st + GA + raddr[mt] + (((kca ^ sxa[mt])) << 4));
#pragma unroll
      for (int g = 0; g < 4; ++g)
        LDSM4(bb[g], st + GB + rbad[g] + (((kcb ^ sxb[g])) << 4));
#pragma unroll
      for (int mt = 0; mt < 4; ++mt)
#pragma unroll
        for (int g = 0; g < 4; ++g) {
          MMA16816F(acc[mt][2 * g], ah[mt], bb[g][0], bb[g][1]);
          MMA16816F(acc[mt][2 * g + 1], ah[mt], bb[g][2], bb[g][3]);
        }
    }

    if (nc < NCH) {
      unsigned char* stn = smem + (nc & 1) * GSTAGE;
#pragma unroll
      for (int half = 0; half < 2; ++half) {
        const float4 p = av[2 * half];
        const float4 q = av[2 * half + 1];
        uint32_t hu[4];
        hu[0] = pack_half2(p.x, p.y);
        hu[1] = pack_half2(p.z, p.w);
        hu[2] = pack_half2(q.x, q.y);
        hu[3] = pack_half2(q.z, q.w);
        const int cc = (aseg >> 3) + half;
        const uint32_t off = aDst + ((uint32_t)(cc ^ aXor) << 4);
        *reinterpret_cast<uint4*>(stn + GA + off) = make_uint4(hu[0], hu[1], hu[2], hu[3]);
      }
    }
  }

  // ---- epilogue: acc -> g_curx ----
#pragma unroll
  for (int mt = 0; mt < 4; ++mt) {
    const int r0 = m0 + wm + mt * 16 + (lane >> 2);
#pragma unroll
    for (int n8 = 0; n8 < 8; ++n8) {
      const int col = wn + n8 * 8 + (lane & 3) * 2;
      *reinterpret_cast<float2*>(g_curx + (size_t)r0 * H + col) =
          make_float2(acc[mt][n8][0], acc[mt][n8][1]);
      *reinterpret_cast<float2*>(g_curx + (size_t)(r0 + 8) * H + col) =
          make_float2(acc[mt][n8][2], acc[mt][n8][3]);
    }
  }
}

// ---------------------------------------------------------------------------
// Kernel 2: BRF recurrence, single-CTA (no cluster), fp16 W_z in smem.
// 128 CTAs x 256 threads; CTA owns batch rows b0, b0+1; thread owns h=tid.
// Emits spike bitmasks to g_zmask; readout moved to scan/loss kernels.
// ---------------------------------------------------------------------------
__global__ void __launch_bounds__(256, 1)
rec_kernel(const float* __restrict__ Wh, const float* __restrict__ omp,
           const float* __restrict__ bop, float* __restrict__ out) {
  extern __shared__ unsigned char smrec[];
  __half* Wz = reinterpret_cast<__half*>(smrec);                 // [j][h]
  uint32_t* zms = reinterpret_cast<uint32_t*>(smrec + REC_WZ_BYTES);  // [2][2][8]

  const int tid = threadIdx.x;
  const int lane = tid & 31;
  const int wq = tid >> 5;
  const int b0 = blockIdx.x * 2;

  {  // load W_z fp16: thread reads its contiguous row segment, writes strided
    const float* src = Wh + (size_t)tid * WHS + I;
#pragma unroll 8
    for (int j = 0; j < 256; ++j) Wz[j * 256 + tid] = __float2half(src[j]);
  }
  if (tid < 32) zms[tid] = 0u;

  const float om = fabsf(omp[tid]);
  const float dmv = DELTA * om;
  const float pom = (-1.f + sqrtf(1.f - dmv * dmv)) / DELTA;
  const float bof = fabsf(bop[tid]);
  float u[2] = {0, 0}, v[2] = {0, 0}, q[2] = {0, 0}, zr[2] = {0, 0};

  // cur prefetch, distance 2
  const float* curb = g_curx + (size_t)b0 * H + tid;
  float cA0 = curb[0], cA1 = curb[H];
  float cB0 = 0.f, cB1 = 0.f;
  {
    const float* c1p = g_curx + ((size_t)B + b0) * H + tid;
    cB0 = c1p[0]; cB1 = c1p[H];
  }

  __syncthreads();

  for (int t = 0; t < T; ++t) {
    const int cbuf = t & 1, nbuf = cbuf ^ 1;
    float cC0 = 0.f, cC1 = 0.f;
    if (t + 2 < T) {
      const float* cp = g_curx + ((size_t)(t + 2) * B + b0) * H + tid;
      cC0 = cp[0]; cC1 = cp[H];
    }

    float a0 = cA0, a1 = cA1;
#pragma unroll
    for (int w = 0; w < 8; ++w) {
      uint32_t m = zms[(cbuf * 2 + 0) * 8 + w];
      while (m) {
        int bp = __ffs(m) - 1; m &= m - 1;
        a0 += __half2float(Wz[((w << 5) + bp) * 256 + tid]);
      }
    }
#pragma unroll
    for (int w = 0; w < 8; ++w) {
      uint32_t m = zms[(cbuf * 2 + 1) * 8 + w];
      while (m) {
        int bp = __ffs(m) - 1; m &= m - 1;
        a1 += __half2float(Wz[((w << 5) + bp) * 256 + tid]);
      }
    }

    const float cw[2] = {a0, a1};
#pragma unroll
    for (int rr = 0; rr < 2; ++rr) {
      float b = pom - bof - q[rr];
      float un = u[rr] + DELTA * (b * u[rr] - om * v[rr] + cw[rr]);
      float vn = v[rr] + DELTA * (om * un + b * v[rr]);
      float z = (un - THETA - q[rr]) > 0.f ? 1.f : 0.f;
      q[rr] = GAMMA * q[rr] + z;
      u[rr] = un; v[rr] = vn; zr[rr] = z;
    }

    const unsigned mk0 = __ballot_sync(0xffffffffu, zr[0] > 0.f);
    const unsigned mk1 = __ballot_sync(0xffffffffu, zr[1] > 0.f);
    if (lane == 0) {
      zms[(nbuf * 2 + 0) * 8 + wq] = mk0;
      zms[(nbuf * 2 + 1) * 8 + wq] = mk1;
      g_zmask[((size_t)t * B + b0) * 8 + wq] = mk0;
      g_zmask[((size_t)t * B + b0 + 1) * 8 + wq] = mk1;
    }
    __syncthreads();
    cA0 = cB0; cA1 = cB1; cB0 = cC0; cB1 = cC1;
  }

#pragma unroll
  for (int rr = 0; rr < 2; ++rr) {
    const size_t idx = (size_t)(b0 + rr) * H + tid;
    out[OFF_ZF + idx] = zr[rr];
    out[OFF_UF + idx] = u[rr];
  }
}

// ---------------------------------------------------------------------------
// Kernel 3: ou scan — warp per batch row, lanes 0..19 hold ou state.
// outputs[t,b,o] and ouf written here.
// ---------------------------------------------------------------------------
__global__ void __launch_bounds__(256, 1)
scan_kernel(const float* __restrict__ Wo, const float* __restrict__ taup,
            float* __restrict__ out) {
  __shared__ float WoT[256 * 20 + 32];
  const int tid = threadIdx.x;
  for (int i = tid; i < 256 * 20; i += 256) {
    const int j = i / 20, o = i - j * 20;
    WoT[i] = Wo[o * H + j];
  }
  __syncthreads();

  const int lid = tid & 31, wid = tid >> 5;
  const int b = blockIdx.x * 8 + wid;
  const float alpha = (lid < 20) ? expf(-DELTA / taup[lid]) : 0.f;
  const float onem = 1.f - alpha;
  float ou = 0.f;

  uint32_t mw = (lid < 8) ? g_zmask[(size_t)b * 8 + lid] : 0u;
  for (int t = 0; t < T; ++t) {
    uint32_t mwn = 0u;
    if (t + 1 < T && lid < 8)
      mwn = g_zmask[((size_t)(t + 1) * B + b) * 8 + lid];
    float s = 0.f;
#pragma unroll
    for (int w = 0; w < 8; ++w) {
      uint32_t word = __shfl_sync(0xffffffffu, mw, w);
      while (word) {
        int bp = __ffs(word) - 1; word &= word - 1;
        s += WoT[((w << 5) + bp) * 20 + lid];
      }
    }
    ou = alpha * ou + onem * s;
    if (lid < 20) out[((size_t)t * B + b) * O + lid] = ou;
    mw = mwn;
  }
  if (lid < 20) out[OFF_OUF + (size_t)b * O + lid] = ou;
}

// ---------------------------------------------------------------------------
// Kernel 4: per-(t,b) log-softmax loss partials (fully parallel)
// ---------------------------------------------------------------------------
__global__ void __launch_bounds__(256)
loss_kernel(const int* __restrict__ Y, const float* __restrict__ out) {
  const int idx = blockIdx.x * 256 + threadIdx.x;  // t*B + b
  if (idx >= T * B) return;
  const float* o20 = out + (size_t)idx * O;
  const int y = Y[idx];
  float m = -1e30f;
#pragma unroll
  for (int o = 0; o < O; ++o) m = fmaxf(m, o20[o]);
  float se = 0.f;
#pragma unroll
  for (int o = 0; o < O; ++o) se += expf(o20[o] - m);
  g_losspart[idx] = -(o20[y] - m - logf(se)) * (1.f / (float)B);
}

// ---------------------------------------------------------------------------
// Kernel 5: deterministic loss reduction
// ---------------------------------------------------------------------------
__global__ void __launch_bounds__(1024) reduce_kernel(float* __restrict__ out) {
  __shared__ float s[1024];
  float acc = 0.f;
  for (int i = threadIdx.x; i < T * B; i += 1024) acc += g_losspart[i];
  s[threadIdx.x] = acc;
  __syncthreads();
  for (int st = 512; st > 0; st >>= 1) {
    if (threadIdx.x < st) s[threadIdx.x] += s[threadIdx.x + st];
    __syncthreads();
  }
  if (threadIdx.x == 0) out[OFF_LOSS] = s[0];
}

// ---------------------------------------------------------------------------
extern "C" void kernel_launch(void* const* d_in, const int* in_sizes, int n_in,
                              void* d_out, int out_size) {
  const float* x = (const float*)d_in[0];
  const int* y = (const int*)d_in[1];
  const float* Wh = (const float*)d_in[2];
  const float* omega = (const float*)d_in[3];
  const float* boff = (const float*)d_in[4];
  const float* Wo = (const float*)d_in[5];
  const float* tau = (const float*)d_in[6];
  float* out = (float*)d_out;

  cudaFuncSetAttribute(gemm_mma_kernel, cudaFuncAttributeMaxDynamicSharedMemorySize,
                       GS_TOTAL);
  cudaFuncSetAttribute(rec_kernel, cudaFuncAttributeMaxDynamicSharedMemorySize,
                       REC_SMEM);

  prep_w_kernel<<<NCH, 256>>>(Wh);
  gemm_mma_kernel<<<(T * B) / 128, 256, GS_TOTAL>>>(x);
  rec_kernel<<<B / 2, 256, REC_SMEM>>>(Wh, omega, boff, out);
  scan_kernel<<<B / 8, 256>>>(Wo, tau, out);
  loss_kernel<<<(T * B + 255) / 256, 256>>>(y, out);
  reduce_kernel<<<1, 1024>>>(out);
}

// round 11
// speedup vs baseline: 4.6506x; 1.3739x over previous
#include <cuda_runtime.h>
#include <cuda_fp16.h>
#include <cstdint>
#include <cstddef>

namespace {
constexpr int T = 1000, B = 256, I = 700, H = 256, O = 20, WHS = I + H;
constexpr float DELTA = 0.01f, GAMMA = 0.9f, THETA = 1.0f;
constexpr size_t OFF_LOSS = (size_t)T * B * O;
constexpr size_t OFF_ZF = OFF_LOSS + 1;
constexpr size_t OFF_UF = OFF_ZF + (size_t)B * H;
constexpr size_t OFF_OUF = OFF_UF + (size_t)B * H;

// ---- mma.sync GEMM config: single-term fp16, 128x256 CTA, x read once ----
constexpr int NCH = 22;                 // K chunks of 32 (K padded to 704)
constexpr int WIMG = 256 * 64;          // 16 KB: one chunk's W image (fp16)
constexpr int GA = 0;                   // A: [128 rows][64B] swizzled (8 KB)
constexpr int GB = 8192;                // B: [256 rows][64B] swizzled (16 KB)
constexpr int GSTAGE = 24576;
constexpr int GS_TOTAL = 2 * GSTAGE;    // 48 KB

// ---- rec kernel smem ----
constexpr int REC_WZ_BYTES = 256 * 256 * 2;        // fp16 W_z [j][h]
constexpr int REC_SMEM = REC_WZ_BYTES + 2 * 2 * 8 * 4 + 64;

// ---- segmented ou scan ----
constexpr int NSEG = 50, SEGL = 20;     // NSEG * SEGL == T
}  // namespace

__device__ float g_curx[(size_t)T * B * H];          // x @ W_x^T
__device__ uint32_t g_zmask[(size_t)T * B * 8];      // spike bitmasks per (t,b)
__device__ float g_losspart[(size_t)T * B];          // per-(t,b) loss partials
__device__ float g_segend[(size_t)NSEG * B * O];     // segment-local ou at seg end
__device__ float g_carry[(size_t)NSEG * B * O];      // carry into each segment
__device__ __align__(128) unsigned char g_wB[NCH * WIMG];  // per-chunk W images

// ---------------------------------------------------------------------------
// helpers
// ---------------------------------------------------------------------------
__device__ __forceinline__ unsigned smem_u32(const void* p) {
  return (unsigned)__cvta_generic_to_shared(p);
}
__device__ __forceinline__ uint32_t pack_half2(float a, float b) {
  __half2 h = __floats2half2_rn(a, b);
  return *reinterpret_cast<uint32_t*>(&h);
}

#define LDSM4(r, addr)                                                        \
  asm volatile("ldmatrix.sync.aligned.m8n8.x4.shared.b16 {%0,%1,%2,%3}, [%4];" \
               : "=r"((r)[0]), "=r"((r)[1]), "=r"((r)[2]), "=r"((r)[3])        \
               : "r"(addr))

#define MMA16816F(d, a, b0, b1)                                               \
  asm volatile(                                                               \
      "mma.sync.aligned.m16n8k16.row.col.f32.f16.f16.f32 "                    \
      "{%0,%1,%2,%3},{%4,%5,%6,%7},{%8,%9},{%0,%1,%2,%3};"                    \
      : "+f"((d)[0]), "+f"((d)[1]), "+f"((d)[2]), "+f"((d)[3])                \
      : "r"((a)[0]), "r"((a)[1]), "r"((a)[2]), "r"((a)[3]), "r"(b0), "r"(b1))

#define CPASYNC16(dst, src)                                                   \
  asm volatile("cp.async.cg.shared.global [%0], [%1], 16;" :: "r"(dst),       \
               "l"(src) : "memory")

// ---------------------------------------------------------------------------
// Kernel 0: W_h[:, :700] -> fp16, pre-swizzled smem-image layout.
// ---------------------------------------------------------------------------
__global__ void prep_w_kernel(const float* __restrict__ Wh) {
  const int chunk = blockIdx.x;
  const int n = threadIdx.x;  // 0..255
  unsigned char* dst = g_wB + (size_t)chunk * WIMG + n * 64;
#pragma unroll
  for (int c = 0; c < 4; ++c) {
    uint32_t u[4];
#pragma unroll
    for (int jj = 0; jj < 4; ++jj) {
      const int k = chunk * 32 + c * 8 + jj * 2;
      float w0 = (k < I) ? Wh[(size_t)n * WHS + k] : 0.f;
      float w1 = (k + 1 < I) ? Wh[(size_t)n * WHS + k + 1] : 0.f;
      u[jj] = pack_half2(w0, w1);
    }
    const int cSw = c ^ ((n >> 1) & 3);
    *reinterpret_cast<uint4*>(dst + cSw * 16) = make_uint4(u[0], u[1], u[2], u[3]);
  }
}

// ---------------------------------------------------------------------------
// Kernel 1: cur_x = x @ W_x^T via mma.sync fp16 (passing, unchanged).
// ---------------------------------------------------------------------------
__global__ __launch_bounds__(256, 1) void gemm_mma_kernel(const float* __restrict__ X) {
  extern __shared__ __align__(1024) unsigned char smem[];
  const uint32_t sb = smem_u32(smem);
  const int tid = threadIdx.x;
  const int lane = tid & 31, wid = tid >> 5;
  const int wm = (wid & 1) * 64, wn = (wid >> 1) * 64;
  const int m0 = blockIdx.x * 128;

  const int arow = tid >> 1;
  const int aseg = (tid & 1) << 4;
  const float* xrow = X + (size_t)(m0 + arow) * I;
  const uint32_t aXor = ((arow >> 1) & 3);
  const uint32_t aDst = (uint32_t)(arow * 64);

  int raddr[4], sxa[4], rbad[4], sxb[4];
#pragma unroll
  for (int mt = 0; mt < 4; ++mt) {
    int r = wm + mt * 16 + (lane & 15);
    raddr[mt] = r * 64;
    sxa[mt] = (r >> 1) & 3;
  }
  const int ca = lane >> 4;
#pragma unroll
  for (int g = 0; g < 4; ++g) {
    int n = wn + g * 16 + (lane & 7) + ((lane >> 4) << 3);
    rbad[g] = n * 64;
    sxb[g] = (n >> 1) & 3;
  }
  const int cb = (lane >> 3) & 1;

  float acc[4][8][4];
#pragma unroll
  for (int mt = 0; mt < 4; ++mt)
#pragma unroll
    for (int n8 = 0; n8 < 8; ++n8)
#pragma unroll
      for (int j = 0; j < 4; ++j) acc[mt][n8][j] = 0.f;

  float4 av[4];

#pragma unroll
  for (int i = 0; i < 4; ++i) {
    const int col = aseg + i * 4;
    av[i] = (col < I) ? *reinterpret_cast<const float4*>(xrow + col)
                      : make_float4(0.f, 0.f, 0.f, 0.f);
  }
  {
#pragma unroll
    for (int i = 0; i < 4; ++i)
      CPASYNC16(sb + GB + tid * 16 + i * 4096, g_wB + tid * 16 + i * 4096);
    asm volatile("cp.async.commit_group;" ::: "memory");
  }
  {
#pragma unroll
    for (int half = 0; half < 2; ++half) {
      const float4 p = av[2 * half];
      const float4 q = av[2 * half + 1];
      uint32_t hu[4];
      hu[0] = pack_half2(p.x, p.y);
      hu[1] = pack_half2(p.z, p.w);
      hu[2] = pack_half2(q.x, q.y);
      hu[3] = pack_half2(q.z, q.w);
      const int cc = (aseg >> 3) + half;
      const uint32_t off = aDst + ((uint32_t)(cc ^ aXor) << 4);
      *reinterpret_cast<uint4*>(smem + GA + off) = make_uint4(hu[0], hu[1], hu[2], hu[3]);
    }
  }

  for (int c = 0; c < NCH; ++c) {
    asm volatile("cp.async.wait_group 0;" ::: "memory");
    __syncthreads();

    const int nc = c + 1;
    if (nc < NCH) {
      const uint32_t nst = sb + (nc & 1) * GSTAGE;
      const unsigned char* src = g_wB + (size_t)nc * WIMG;
#pragma unroll
      for (int i = 0; i < 4; ++i)
        CPASYNC16(nst + GB + tid * 16 + i * 4096, src + tid * 16 + i * 4096);
      asm volatile("cp.async.commit_group;" ::: "memory");
      const int colbase = nc * 32 + aseg;
#pragma unroll
      for (int i = 0; i < 4; ++i) {
        const int col = colbase + i * 4;
        av[i] = (col < I) ? *reinterpret_cast<const float4*>(xrow + col)
                          : make_float4(0.f, 0.f, 0.f, 0.f);
      }
    }

    const uint32_t st = sb + (c & 1) * GSTAGE;
#pragma unroll
    for (int k16 = 0; k16 < 2; ++k16) {
      uint32_t ah[4][4], bb[4][4];
      const int kca = k16 * 2 + ca;
      const int kcb = k16 * 2 + cb;
#pragma unroll
      for (int mt = 0; mt < 4; ++mt)
        LDSM4(ah[mt], st + GA + raddr[mt] + (((kca ^ sxa[mt])) << 4));
#pragma unroll
      for (int g = 0; g < 4; ++g)
        LDSM4(bb[g], st + GB + rbad[g] + (((kcb ^ sxb[g])) << 4));
#pragma unroll
      for (int mt = 0; mt < 4; ++mt)
#pragma unroll
        for (int g = 0; g < 4; ++g) {
          MMA16816F(acc[mt][2 * g], ah[mt], bb[g][0], bb[g][1]);
          MMA16816F(acc[mt][2 * g + 1], ah[mt], bb[g][2], bb[g][3]);
        }
    }

    if (nc < NCH) {
      unsigned char* stn = smem + (nc & 1) * GSTAGE;
#pragma unroll
      for (int half = 0; half < 2; ++half) {
        const float4 p = av[2 * half];
        const float4 q = av[2 * half + 1];
        uint32_t hu[4];
        hu[0] = pack_half2(p.x, p.y);
        hu[1] = pack_half2(p.z, p.w);
        hu[2] = pack_half2(q.x, q.y);
        hu[3] = pack_half2(q.z, q.w);
        const int cc = (aseg >> 3) + half;
        const uint32_t off = aDst + ((uint32_t)(cc ^ aXor) << 4);
        *reinterpret_cast<uint4*>(stn + GA + off) = make_uint4(hu[0], hu[1], hu[2], hu[3]);
      }
    }
  }

#pragma unroll
  for (int mt = 0; mt < 4; ++mt) {
    const int r0 = m0 + wm + mt * 16 + (lane >> 2);
#pragma unroll
    for (int n8 = 0; n8 < 8; ++n8) {
      const int col = wn + n8 * 8 + (lane & 3) * 2;
      *reinterpret_cast<float2*>(g_curx + (size_t)r0 * H + col) =
          make_float2(acc[mt][n8][0], acc[mt][n8][1]);
      *reinterpret_cast<float2*>(g_curx + (size_t)(r0 + 8) * H + col) =
          make_float2(acc[mt][n8][2], acc[mt][n8][3]);
    }
  }
}

// ---------------------------------------------------------------------------
// Kernel 2: BRF recurrence, single-CTA, fp16 W_z in smem (passing, unchanged).
// ---------------------------------------------------------------------------
__global__ void __launch_bounds__(256, 1)
rec_kernel(const float* __restrict__ Wh, const float* __restrict__ omp,
           const float* __restrict__ bop, float* __restrict__ out) {
  extern __shared__ unsigned char smrec[];
  __half* Wz = reinterpret_cast<__half*>(smrec);                 // [j][h]
  uint32_t* zms = reinterpret_cast<uint32_t*>(smrec + REC_WZ_BYTES);  // [2][2][8]

  const int tid = threadIdx.x;
  const int lane = tid & 31;
  const int wq = tid >> 5;
  const int b0 = blockIdx.x * 2;

  {
    const float* src = Wh + (size_t)tid * WHS + I;
#pragma unroll 8
    for (int j = 0; j < 256; ++j) Wz[j * 256 + tid] = __float2half(src[j]);
  }
  if (tid < 32) zms[tid] = 0u;

  const float om = fabsf(omp[tid]);
  const float dmv = DELTA * om;
  const float pom = (-1.f + sqrtf(1.f - dmv * dmv)) / DELTA;
  const float bof = fabsf(bop[tid]);
  float u[2] = {0, 0}, v[2] = {0, 0}, q[2] = {0, 0}, zr[2] = {0, 0};

  const float* curb = g_curx + (size_t)b0 * H + tid;
  float cA0 = curb[0], cA1 = curb[H];
  float cB0 = 0.f, cB1 = 0.f;
  {
    const float* c1p = g_curx + ((size_t)B + b0) * H + tid;
    cB0 = c1p[0]; cB1 = c1p[H];
  }

  __syncthreads();

  for (int t = 0; t < T; ++t) {
    const int cbuf = t & 1, nbuf = cbuf ^ 1;
    float cC0 = 0.f, cC1 = 0.f;
    if (t + 2 < T) {
      const float* cp = g_curx + ((size_t)(t + 2) * B + b0) * H + tid;
      cC0 = cp[0]; cC1 = cp[H];
    }

    float a0 = cA0, a1 = cA1;
#pragma unroll
    for (int w = 0; w < 8; ++w) {
      uint32_t m = zms[(cbuf * 2 + 0) * 8 + w];
      while (m) {
        int bp = __ffs(m) - 1; m &= m - 1;
        a0 += __half2float(Wz[((w << 5) + bp) * 256 + tid]);
      }
    }
#pragma unroll
    for (int w = 0; w < 8; ++w) {
      uint32_t m = zms[(cbuf * 2 + 1) * 8 + w];
      while (m) {
        int bp = __ffs(m) - 1; m &= m - 1;
        a1 += __half2float(Wz[((w << 5) + bp) * 256 + tid]);
      }
    }

    const float cw[2] = {a0, a1};
#pragma unroll
    for (int rr = 0; rr < 2; ++rr) {
      float b = pom - bof - q[rr];
      float un = u[rr] + DELTA * (b * u[rr] - om * v[rr] + cw[rr]);
      float vn = v[rr] + DELTA * (om * un + b * v[rr]);
      float z = (un - THETA - q[rr]) > 0.f ? 1.f : 0.f;
      q[rr] = GAMMA * q[rr] + z;
      u[rr] = un; v[rr] = vn; zr[rr] = z;
    }

    const unsigned mk0 = __ballot_sync(0xffffffffu, zr[0] > 0.f);
    const unsigned mk1 = __ballot_sync(0xffffffffu, zr[1] > 0.f);
    if (lane == 0) {
      zms[(nbuf * 2 + 0) * 8 + wq] = mk0;
      zms[(nbuf * 2 + 1) * 8 + wq] = mk1;
      g_zmask[((size_t)t * B + b0) * 8 + wq] = mk0;
      g_zmask[((size_t)t * B + b0 + 1) * 8 + wq] = mk1;
    }
    __syncthreads();
    cA0 = cB0; cA1 = cB1; cB0 = cC0; cB1 = cC1;
  }

#pragma unroll
  for (int rr = 0; rr < 2; ++rr) {
    const size_t idx = (size_t)(b0 + rr) * H + tid;
    out[OFF_ZF + idx] = zr[rr];
    out[OFF_UF + idx] = u[rr];
  }
}

// ---------------------------------------------------------------------------
// Kernel 3a: segment-local ou scan. Warp per (segment, row); 1600 CTAs.
// Writes local scan values to out[t,b,:] and segment-end to g_segend.
// ---------------------------------------------------------------------------
__global__ void __launch_bounds__(256, 1)
scan_seg_kernel(const float* __restrict__ Wo, const float* __restrict__ taup,
                float* __restrict__ out) {
  __shared__ float WoT[256 * 20 + 32];
  const int tid = threadIdx.x;
  for (int i = tid; i < 256 * 20; i += 256) {
    const int j = i / 20, o = i - j * 20;
    WoT[i] = Wo[o * H + j];
  }
  __syncthreads();

  const int lid = tid & 31;
  const int gw = blockIdx.x * 8 + (tid >> 5);  // 0..NSEG*B-1
  const int b = gw & (B - 1);
  const int seg = gw >> 8;
  const int t0 = seg * SEGL;
  const float alpha = (lid < 20) ? expf(-DELTA / taup[lid]) : 0.f;
  const float onem = 1.f - alpha;
  float l = 0.f;

  uint32_t mw = (lid < 8) ? g_zmask[((size_t)t0 * B + b) * 8 + lid] : 0u;
  for (int k = 0; k < SEGL; ++k) {
    const int t = t0 + k;
    uint32_t mwn = 0u;
    if (k + 1 < SEGL && lid < 8)
      mwn = g_zmask[((size_t)(t + 1) * B + b) * 8 + lid];
    float s = 0.f;
#pragma unroll
    for (int w = 0; w < 8; ++w) {
      uint32_t word = __shfl_sync(0xffffffffu, mw, w);
      while (word) {
        int bp = __ffs(word) - 1; word &= word - 1;
        s += WoT[((w << 5) + bp) * 20 + lid];
      }
    }
    l = alpha * l + onem * s;
    if (lid < 20) out[((size_t)t * B + b) * O + lid] = l;
    mw = mwn;
  }
  if (lid < 20) g_segend[((size_t)seg * B + b) * O + lid] = l;
}

// ---------------------------------------------------------------------------
// Kernel 3b: serial carry over segments (B*O threads), writes ouf.
// ---------------------------------------------------------------------------
__global__ void __launch_bounds__(256)
carry_kernel(const float* __restrict__ taup, float* __restrict__ out) {
  const int idx = blockIdx.x * 256 + threadIdx.x;
  if (idx >= B * O) return;
  const int b = idx / O, o = idx - b * O;
  const float aL = expf(-DELTA * (float)SEGL / taup[o]);
  float c = 0.f;
  for (int s = 0; s < NSEG; ++s) {
    g_carry[((size_t)s * B + b) * O + o] = c;
    c = c * aL + g_segend[((size_t)s * B + b) * O + o];
  }
  out[OFF_OUF + (size_t)b * O + o] = c;
}

// ---------------------------------------------------------------------------
// Kernel 3c: fixup — out[t,b,o] += alpha^(k+1) * carry[seg,b,o] (skip if 0).
// ---------------------------------------------------------------------------
__global__ void __launch_bounds__(256)
fixup_kernel(const float* __restrict__ taup, float* __restrict__ out) {
  const int idx = blockIdx.x * 256 + threadIdx.x;  // (t*B+b)*O+o
  if (idx >= T * B * O) return;
  const int o = idx % O;
  const int tb = idx / O;
  const int t = tb / B, b = tb - t * B;
  const int seg = t / SEGL, k = t - seg * SEGL;
  const float c = g_carry[((size_t)seg * B + b) * O + o];
  if (c != 0.f) {
    const float alpha = expf(-DELTA / taup[o]);
    out[idx] += powf(alpha, (float)(k + 1)) * c;
  }
}

// ---------------------------------------------------------------------------
// Kernel 4: per-(t,b) log-softmax loss partials (fully parallel)
// ---------------------------------------------------------------------------
__global__ void __launch_bounds__(256)
loss_kernel(const int* __restrict__ Y, const float* __restrict__ out) {
  const int idx = blockIdx.x * 256 + threadIdx.x;  // t*B + b
  if (idx >= T * B) return;
  const float* o20 = out + (size_t)idx * O;
  const int y = Y[idx];
  float m = -1e30f;
#pragma unroll
  for (int o = 0; o < O; ++o) m = fmaxf(m, o20[o]);
  float se = 0.f;
#pragma unroll
  for (int o = 0; o < O; ++o) se += expf(o20[o] - m);
  g_losspart[idx] = -(o20[y] - m - logf(se)) * (1.f / (float)B);
}

// ---------------------------------------------------------------------------
// Kernel 5: deterministic loss reduction
// ---------------------------------------------------------------------------
__global__ void __launch_bounds__(1024) reduce_kernel(float* __restrict__ out) {
  __shared__ float s[1024];
  float acc = 0.f;
  for (int i = threadIdx.x; i < T * B; i += 1024) acc += g_losspart[i];
  s[threadIdx.x] = acc;
  __syncthreads();
  for (int st = 512; st > 0; st >>= 1) {
    if (threadIdx.x < st) s[threadIdx.x] += s[threadIdx.x + st];
    __syncthreads();
  }
  if (threadIdx.x == 0) out[OFF_LOSS] = s[0];
}

// ---------------------------------------------------------------------------
extern "C" void kernel_launch(void* const* d_in, const int* in_sizes, int n_in,
                              void* d_out, int out_size) {
  const float* x = (const float*)d_in[0];
  const int* y = (const int*)d_in[1];
  const float* Wh = (const float*)d_in[2];
  const float* omega = (const float*)d_in[3];
  const float* boff = (const float*)d_in[4];
  const float* Wo = (const float*)d_in[5];
  const float* tau = (const float*)d_in[6];
  float* out = (float*)d_out;

  cudaFuncSetAttribute(gemm_mma_kernel, cudaFuncAttributeMaxDynamicSharedMemorySize,
                       GS_TOTAL);
  cudaFuncSetAttribute(rec_kernel, cudaFuncAttributeMaxDynamicSharedMemorySize,
                       REC_SMEM);

  prep_w_kernel<<<NCH, 256>>>(Wh);
  gemm_mma_kernel<<<(T * B) / 128, 256, GS_TOTAL>>>(x);
  rec_kernel<<<B / 2, 256, REC_SMEM>>>(Wh, omega, boff, out);
  scan_seg_kernel<<<NSEG * B / 8, 256>>>(Wo, tau, out);
  carry_kernel<<<(B * O + 255) / 256, 256>>>(tau, out);
  fixup_kernel<<<(T * B * O + 255) / 256, 256>>>(tau, out);
  loss_kernel<<<(T * B + 255) / 256, 256>>>(y, out);
  reduce_kernel<<<1, 1024>>>(out);
}

// round 12
// speedup vs baseline: 4.6685x; 1.0039x over previous
#include <cuda_runtime.h>
#include <cuda_fp16.h>
#include <cstdint>
#include <cstddef>

namespace {
constexpr int T = 1000, B = 256, I = 700, H = 256, O = 20, WHS = I + H;
constexpr float DELTA = 0.01f, GAMMA = 0.9f, THETA = 1.0f;
constexpr size_t OFF_LOSS = (size_t)T * B * O;
constexpr size_t OFF_ZF = OFF_LOSS + 1;
constexpr size_t OFF_UF = OFF_ZF + (size_t)B * H;
constexpr size_t OFF_OUF = OFF_UF + (size_t)B * H;

// ---- mma.sync GEMM config: single-term fp16, 128x256 CTA, x read once ----
constexpr int NCH = 22;                 // K chunks of 32 (K padded to 704)
constexpr int WIMG = 256 * 64;          // 16 KB: one chunk's W image (fp16)
constexpr int GA = 0;                   // A: [128 rows][64B] swizzled (8 KB)
constexpr int GB = 8192;                // B: [256 rows][64B] swizzled (16 KB)
constexpr int GSTAGE = 24576;
constexpr int GS_TOTAL = 2 * GSTAGE;    // 48 KB

// ---- rec kernel smem ----
constexpr int REC_WZ_BYTES = 256 * 256 * 2;        // fp16 W_z [j][h]
constexpr int REC_SMEM = REC_WZ_BYTES + 2 * 2 * 8 * 4 + 64;

// ---- segmented ou scan ----
constexpr int NSEG = 50, SEGL = 20;     // NSEG * SEGL == T
}  // namespace

__device__ float g_curx[(size_t)T * B * H];          // x @ W_x^T
__device__ uint32_t g_zmask[(size_t)T * B * 8];      // spike bitmasks per (t,b)
__device__ float g_losspart[(size_t)T * B];          // per-(t,b) loss partials
__device__ float g_segend[(size_t)NSEG * B * O];     // segment-local ou at seg end
__device__ float g_carry[(size_t)NSEG * B * O];      // carry into each segment
__device__ __align__(128) unsigned char g_wB[NCH * WIMG];  // per-chunk W images

// ---------------------------------------------------------------------------
// helpers
// ---------------------------------------------------------------------------
__device__ __forceinline__ unsigned smem_u32(const void* p) {
  return (unsigned)__cvta_generic_to_shared(p);
}
__device__ __forceinline__ uint32_t pack_half2(float a, float b) {
  __half2 h = __floats2half2_rn(a, b);
  return *reinterpret_cast<uint32_t*>(&h);
}

#define LDSM4(r, addr)                                                        \
  asm volatile("ldmatrix.sync.aligned.m8n8.x4.shared.b16 {%0,%1,%2,%3}, [%4];" \
               : "=r"((r)[0]), "=r"((r)[1]), "=r"((r)[2]), "=r"((r)[3])        \
               : "r"(addr))

#define MMA16816F(d, a, b0, b1)                                               \
  asm volatile(                                                               \
      "mma.sync.aligned.m16n8k16.row.col.f32.f16.f16.f32 "                    \
      "{%0,%1,%2,%3},{%4,%5,%6,%7},{%8,%9},{%0,%1,%2,%3};"                    \
      : "+f"((d)[0]), "+f"((d)[1]), "+f"((d)[2]), "+f"((d)[3])                \
      : "r"((a)[0]), "r"((a)[1]), "r"((a)[2]), "r"((a)[3]), "r"(b0), "r"(b1))

#define CPASYNC16(dst, src)                                                   \
  asm volatile("cp.async.cg.shared.global [%0], [%1], 16;" :: "r"(dst),       \
               "l"(src) : "memory")

// ---------------------------------------------------------------------------
// Kernel 0: W_h[:, :700] -> fp16, pre-swizzled smem-image layout.
// ---------------------------------------------------------------------------
__global__ void prep_w_kernel(const float* __restrict__ Wh) {
  const int chunk = blockIdx.x;
  const int n = threadIdx.x;  // 0..255
  unsigned char* dst = g_wB + (size_t)chunk * WIMG + n * 64;
#pragma unroll
  for (int c = 0; c < 4; ++c) {
    uint32_t u[4];
#pragma unroll
    for (int jj = 0; jj < 4; ++jj) {
      const int k = chunk * 32 + c * 8 + jj * 2;
      float w0 = (k < I) ? Wh[(size_t)n * WHS + k] : 0.f;
      float w1 = (k + 1 < I) ? Wh[(size_t)n * WHS + k + 1] : 0.f;
      u[jj] = pack_half2(w0, w1);
    }
    const int cSw = c ^ ((n >> 1) & 3);
    *reinterpret_cast<uint4*>(dst + cSw * 16) = make_uint4(u[0], u[1], u[2], u[3]);
  }
}

// ---------------------------------------------------------------------------
// Kernel 1: cur_x = x @ W_x^T via mma.sync fp16 (passing, unchanged).
// ---------------------------------------------------------------------------
__global__ __launch_bounds__(256, 1) void gemm_mma_kernel(const float* __restrict__ X) {
  extern __shared__ __align__(1024) unsigned char smem[];
  const uint32_t sb = smem_u32(smem);
  const int tid = threadIdx.x;
  const int lane = tid & 31, wid = tid >> 5;
  const int wm = (wid & 1) * 64, wn = (wid >> 1) * 64;
  const int m0 = blockIdx.x * 128;

  const int arow = tid >> 1;
  const int aseg = (tid & 1) << 4;
  const float* xrow = X + (size_t)(m0 + arow) * I;
  const uint32_t aXor = ((arow >> 1) & 3);
  const uint32_t aDst = (uint32_t)(arow * 64);

  int raddr[4], sxa[4], rbad[4], sxb[4];
#pragma unroll
  for (int mt = 0; mt < 4; ++mt) {
    int r = wm + mt * 16 + (lane & 15);
    raddr[mt] = r * 64;
    sxa[mt] = (r >> 1) & 3;
  }
  const int ca = lane >> 4;
#pragma unroll
  for (int g = 0; g < 4; ++g) {
    int n = wn + g * 16 + (lane & 7) + ((lane >> 4) << 3);
    rbad[g] = n * 64;
    sxb[g] = (n >> 1) & 3;
  }
  const int cb = (lane >> 3) & 1;

  float acc[4][8][4];
#pragma unroll
  for (int mt = 0; mt < 4; ++mt)
#pragma unroll
    for (int n8 = 0; n8 < 8; ++n8)
#pragma unroll
      for (int j = 0; j < 4; ++j) acc[mt][n8][j] = 0.f;

  float4 av[4];

#pragma unroll
  for (int i = 0; i < 4; ++i) {
    const int col = aseg + i * 4;
    av[i] = (col < I) ? *reinterpret_cast<const float4*>(xrow + col)
                      : make_float4(0.f, 0.f, 0.f, 0.f);
  }
  {
#pragma unroll
    for (int i = 0; i < 4; ++i)
      CPASYNC16(sb + GB + tid * 16 + i * 4096, g_wB + tid * 16 + i * 4096);
    asm volatile("cp.async.commit_group;" ::: "memory");
  }
  {
#pragma unroll
    for (int half = 0; half < 2; ++half) {
      const float4 p = av[2 * half];
      const float4 q = av[2 * half + 1];
      uint32_t hu[4];
      hu[0] = pack_half2(p.x, p.y);
      hu[1] = pack_half2(p.z, p.w);
      hu[2] = pack_half2(q.x, q.y);
      hu[3] = pack_half2(q.z, q.w);
      const int cc = (aseg >> 3) + half;
      const uint32_t off = aDst + ((uint32_t)(cc ^ aXor) << 4);
      *reinterpret_cast<uint4*>(smem + GA + off) = make_uint4(hu[0], hu[1], hu[2], hu[3]);
    }
  }

  for (int c = 0; c < NCH; ++c) {
    asm volatile("cp.async.wait_group 0;" ::: "memory");
    __syncthreads();

    const int nc = c + 1;
    if (nc < NCH) {
      const uint32_t nst = sb + (nc & 1) * GSTAGE;
      const unsigned char* src = g_wB + (size_t)nc * WIMG;
#pragma unroll
      for (int i = 0; i < 4; ++i)
        CPASYNC16(nst + GB + tid * 16 + i * 4096, src + tid * 16 + i * 4096);
      asm volatile("cp.async.commit_group;" ::: "memory");
      const int colbase = nc * 32 + aseg;
#pragma unroll
      for (int i = 0; i < 4; ++i) {
        const int col = colbase + i * 4;
        av[i] = (col < I) ? *reinterpret_cast<const float4*>(xrow + col)
                          : make_float4(0.f, 0.f, 0.f, 0.f);
      }
    }

    const uint32_t st = sb + (c & 1) * GSTAGE;
#pragma unroll
    for (int k16 = 0; k16 < 2; ++k16) {
      uint32_t ah[4][4], bb[4][4];
      const int kca = k16 * 2 + ca;
      const int kcb = k16 * 2 + cb;
#pragma unroll
      for (int mt = 0; mt < 4; ++mt)
        LDSM4(ah[mt], st + GA + raddr[mt] + (((kca ^ sxa[mt])) << 4));
#pragma unroll
      for (int g = 0; g < 4; ++g)
        LDSM4(bb[g], st + GB + rbad[g] + (((kcb ^ sxb[g])) << 4));
#pragma unroll
      for (int mt = 0; mt < 4; ++mt)
#pragma unroll
        for (int g = 0; g < 4; ++g) {
          MMA16816F(acc[mt][2 * g], ah[mt], bb[g][0], bb[g][1]);
          MMA16816F(acc[mt][2 * g + 1], ah[mt], bb[g][2], bb[g][3]);
        }
    }

    if (nc < NCH) {
      unsigned char* stn = smem + (nc & 1) * GSTAGE;
#pragma unroll
      for (int half = 0; half < 2; ++half) {
        const float4 p = av[2 * half];
        const float4 q = av[2 * half + 1];
        uint32_t hu[4];
        hu[0] = pack_half2(p.x, p.y);
        hu[1] = pack_half2(p.z, p.w);
        hu[2] = pack_half2(q.x, q.y);
        hu[3] = pack_half2(q.z, q.w);
        const int cc = (aseg >> 3) + half;
        const uint32_t off = aDst + ((uint32_t)(cc ^ aXor) << 4);
        *reinterpret_cast<uint4*>(stn + GA + off) = make_uint4(hu[0], hu[1], hu[2], hu[3]);
      }
    }
  }

#pragma unroll
  for (int mt = 0; mt < 4; ++mt) {
    const int r0 = m0 + wm + mt * 16 + (lane >> 2);
#pragma unroll
    for (int n8 = 0; n8 < 8; ++n8) {
      const int col = wn + n8 * 8 + (lane & 3) * 2;
      *reinterpret_cast<float2*>(g_curx + (size_t)r0 * H + col) =
          make_float2(acc[mt][n8][0], acc[mt][n8][1]);
      *reinterpret_cast<float2*>(g_curx + (size_t)(r0 + 8) * H + col) =
          make_float2(acc[mt][n8][2], acc[mt][n8][3]);
    }
  }
}

// ---------------------------------------------------------------------------
// Kernel 2: BRF recurrence, single-CTA, fp16 W_z in smem.
// Fast-path: __syncthreads_or tracks "any spike last step"; when false the
// mask-scan loops are skipped entirely. Prefetch distance 3 covers DRAM lat.
// ---------------------------------------------------------------------------
__global__ void __launch_bounds__(256, 1)
rec_kernel(const float* __restrict__ Wh, const float* __restrict__ omp,
           const float* __restrict__ bop, float* __restrict__ out) {
  extern __shared__ unsigned char smrec[];
  __half* Wz = reinterpret_cast<__half*>(smrec);                 // [j][h]
  uint32_t* zms = reinterpret_cast<uint32_t*>(smrec + REC_WZ_BYTES);  // [2][2][8]

  const int tid = threadIdx.x;
  const int lane = tid & 31;
  const int wq = tid >> 5;
  const int b0 = blockIdx.x * 2;

  {
    const float* src = Wh + (size_t)tid * WHS + I;
#pragma unroll 8
    for (int j = 0; j < 256; ++j) Wz[j * 256 + tid] = __float2half(src[j]);
  }
  if (tid < 32) zms[tid] = 0u;

  const float om = fabsf(omp[tid]);
  const float dmv = DELTA * om;
  const float pom = (-1.f + sqrtf(1.f - dmv * dmv)) / DELTA;
  const float bof = fabsf(bop[tid]);
  float u[2] = {0, 0}, v[2] = {0, 0}, q[2] = {0, 0}, zr[2] = {0, 0};

  // cur prefetch pipeline, distance 3: A=t, Bv=t+1, Cv=t+2
  float cA0, cA1, cB0 = 0.f, cB1 = 0.f, cC0 = 0.f, cC1 = 0.f;
  {
    const float* p0 = g_curx + (size_t)b0 * H + tid;
    cA0 = p0[0]; cA1 = p0[H];
    const float* p1 = g_curx + ((size_t)B + b0) * H + tid;
    cB0 = p1[0]; cB1 = p1[H];
    const float* p2 = g_curx + ((size_t)2 * B + b0) * H + tid;
    cC0 = p2[0]; cC1 = p2[H];
  }
  int anyPrev = 0;

  __syncthreads();

  for (int t = 0; t < T; ++t) {
    const int cbuf = t & 1, nbuf = cbuf ^ 1;
    float cD0 = 0.f, cD1 = 0.f;
    if (t + 3 < T) {
      const float* cp = g_curx + ((size_t)(t + 3) * B + b0) * H + tid;
      cD0 = cp[0]; cD1 = cp[H];
    }

    float a0 = cA0, a1 = cA1;
    if (anyPrev) {  // sparse z_{t-1} @ W_z^T (skipped when no spikes)
#pragma unroll
      for (int w = 0; w < 8; ++w) {
        uint32_t m = zms[(cbuf * 2 + 0) * 8 + w];
        while (m) {
          int bp = __ffs(m) - 1; m &= m - 1;
          a0 += __half2float(Wz[((w << 5) + bp) * 256 + tid]);
        }
      }
#pragma unroll
      for (int w = 0; w < 8; ++w) {
        uint32_t m = zms[(cbuf * 2 + 1) * 8 + w];
        while (m) {
          int bp = __ffs(m) - 1; m &= m - 1;
          a1 += __half2float(Wz[((w << 5) + bp) * 256 + tid]);
        }
      }
    }

#pragma unroll
    for (int rr = 0; rr < 2; ++rr) {
      const float cw = rr ? a1 : a0;
      float b = pom - bof - q[rr];
      float un = u[rr] + DELTA * (b * u[rr] - om * v[rr] + cw);
      float vn = v[rr] + DELTA * (om * un + b * v[rr]);
      float z = (un - THETA - q[rr]) > 0.f ? 1.f : 0.f;
      q[rr] = GAMMA * q[rr] + z;
      u[rr] = un; v[rr] = vn; zr[rr] = z;
    }

    const unsigned mk0 = __ballot_sync(0xffffffffu, zr[0] > 0.f);
    const unsigned mk1 = __ballot_sync(0xffffffffu, zr[1] > 0.f);
    if (lane == 0) {
      zms[(nbuf * 2 + 0) * 8 + wq] = mk0;
      zms[(nbuf * 2 + 1) * 8 + wq] = mk1;
      g_zmask[((size_t)t * B + b0) * 8 + wq] = mk0;
      g_zmask[((size_t)t * B + b0 + 1) * 8 + wq] = mk1;
    }
    anyPrev = __syncthreads_or((int)(mk0 | mk1));
    cA0 = cB0; cA1 = cB1; cB0 = cC0; cB1 = cC1; cC0 = cD0; cC1 = cD1;
  }

#pragma unroll
  for (int rr = 0; rr < 2; ++rr) {
    const size_t idx = (size_t)(b0 + rr) * H + tid;
    out[OFF_ZF + idx] = zr[rr];
    out[OFF_UF + idx] = u[rr];
  }
}

// ---------------------------------------------------------------------------
// Kernel 3a: segment-local ou scan. Warp per (segment, row); 1600 CTAs.
// ---------------------------------------------------------------------------
__global__ void __launch_bounds__(256, 1)
scan_seg_kernel(const float* __restrict__ Wo, const float* __restrict__ taup,
                float* __restrict__ out) {
  __shared__ float WoT[256 * 20 + 32];
  const int tid = threadIdx.x;
  for (int i = tid; i < 256 * 20; i += 256) {
    const int j = i / 20, o = i - j * 20;
    WoT[i] = Wo[o * H + j];
  }
  __syncthreads();

  const int lid = tid & 31;
  const int gw = blockIdx.x * 8 + (tid >> 5);  // 0..NSEG*B-1
  const int b = gw & (B - 1);
  const int seg = gw >> 8;
  const int t0 = seg * SEGL;
  const float alpha = (lid < 20) ? expf(-DELTA / taup[lid]) : 0.f;
  const float onem = 1.f - alpha;
  float l = 0.f;

  uint32_t mw = (lid < 8) ? g_zmask[((size_t)t0 * B + b) * 8 + lid] : 0u;
  for (int k = 0; k < SEGL; ++k) {
    const int t = t0 + k;
    uint32_t mwn = 0u;
    if (k + 1 < SEGL && lid < 8)
      mwn = g_zmask[((size_t)(t + 1) * B + b) * 8 + lid];
    float s = 0.f;
#pragma unroll
    for (int w = 0; w < 8; ++w) {
      uint32_t word = __shfl_sync(0xffffffffu, mw, w);
      while (word) {
        int bp = __ffs(word) - 1; word &= word - 1;
        s += WoT[((w << 5) + bp) * 20 + lid];
      }
    }
    l = alpha * l + onem * s;
    if (lid < 20) out[((size_t)t * B + b) * O + lid] = l;
    mw = mwn;
  }
  if (lid < 20) g_segend[((size_t)seg * B + b) * O + lid] = l;
}

// ---------------------------------------------------------------------------
// Kernel 3b: serial carry over segments (B*O threads), writes ouf.
// ---------------------------------------------------------------------------
__global__ void __launch_bounds__(256)
carry_kernel(const float* __restrict__ taup, float* __restrict__ out) {
  const int idx = blockIdx.x * 256 + threadIdx.x;
  if (idx >= B * O) return;
  const int b = idx / O, o = idx - b * O;
  const float aL = expf(-DELTA * (float)SEGL / taup[o]);
  float c = 0.f;
  for (int s = 0; s < NSEG; ++s) {
    g_carry[((size_t)s * B + b) * O + o] = c;
    c = c * aL + g_segend[((size_t)s * B + b) * O + o];
  }
  out[OFF_OUF + (size_t)b * O + o] = c;
}

// ---------------------------------------------------------------------------
// Kernel 3c: fixup — out[t,b,o] += alpha^(k+1) * carry[seg,b,o] (skip if 0).
// ---------------------------------------------------------------------------
__global__ void __launch_bounds__(256)
fixup_kernel(const float* __restrict__ taup, float* __restrict__ out) {
  const int idx = blockIdx.x * 256 + threadIdx.x;  // (t*B+b)*O+o
  if (idx >= T * B * O) return;
  const int o = idx % O;
  const int tb = idx / O;
  const int t = tb / B, b = tb - t * B;
  const int seg = t / SEGL, k = t - seg * SEGL;
  const float c = g_carry[((size_t)seg * B + b) * O + o];
  if (c != 0.f) {
    const float alpha = expf(-DELTA / taup[o]);
    out[idx] += powf(alpha, (float)(k + 1)) * c;
  }
}

// ---------------------------------------------------------------------------
// Kernel 4: per-(t,b) log-softmax loss partials (fully parallel)
// ---------------------------------------------------------------------------
__global__ void __launch_bounds__(256)
loss_kernel(const int* __restrict__ Y, const float* __restrict__ out) {
  const int idx = blockIdx.x * 256 + threadIdx.x;  // t*B + b
  if (idx >= T * B) return;
  const float* o20 = out + (size_t)idx * O;
  const int y = Y[idx];
  float m = -1e30f;
#pragma unroll
  for (int o = 0; o < O; ++o) m = fmaxf(m, o20[o]);
  float se = 0.f;
#pragma unroll
  for (int o = 0; o < O; ++o) se += expf(o20[o] - m);
  g_losspart[idx] = -(o20[y] - m - logf(se)) * (1.f / (float)B);
}

// ---------------------------------------------------------------------------
// Kernel 5: deterministic loss reduction
// ---------------------------------------------------------------------------
__global__ void __launch_bounds__(1024) reduce_kernel(float* __restrict__ out) {
  __shared__ float s[1024];
  float acc = 0.f;
  for (int i = threadIdx.x; i < T * B; i += 1024) acc += g_losspart[i];
  s[threadIdx.x] = acc;
  __syncthreads();
  for (int st = 512; st > 0; st >>= 1) {
    if (threadIdx.x < st) s[threadIdx.x] += s[threadIdx.x + st];
    __syncthreads();
  }
  if (threadIdx.x == 0) out[OFF_LOSS] = s[0];
}

// ---------------------------------------------------------------------------
extern "C" void kernel_launch(void* const* d_in, const int* in_sizes, int n_in,
                              void* d_out, int out_size) {
  const float* x = (const float*)d_in[0];
  const int* y = (const int*)d_in[1];
  const float* Wh = (const float*)d_in[2];
  const float* omega = (const float*)d_in[3];
  const float* boff = (const float*)d_in[4];
  const float* Wo = (const float*)d_in[5];
  const float* tau = (const float*)d_in[6];
  float* out = (float*)d_out;

  cudaFuncSetAttribute(gemm_mma_kernel, cudaFuncAttributeMaxDynamicSharedMemorySize,
                       GS_TOTAL);
  cudaFuncSetAttribute(rec_kernel, cudaFuncAttributeMaxDynamicSharedMemorySize,
                       REC_SMEM);

  prep_w_kernel<<<NCH, 256>>>(Wh);
  gemm_mma_kernel<<<(T * B) / 128, 256, GS_TOTAL>>>(x);
  rec_kernel<<<B / 2, 256, REC_SMEM>>>(Wh, omega, boff, out);
  scan_seg_kernel<<<NSEG * B / 8, 256>>>(Wo, tau, out);
  carry_kernel<<<(B * O + 255) / 256, 256>>>(tau, out);
  fixup_kernel<<<(T * B * O + 255) / 256, 256>>>(tau, out);
  loss_kernel<<<(T * B + 255) / 256, 256>>>(y, out);
  reduce_kernel<<<1, 1024>>>(out);
}

// round 13
// speedup vs baseline: 7.9780x; 1.7089x over previous
#include <cuda_runtime.h>
#include <cuda_fp16.h>
#include <cstdint>
#include <cstddef>

namespace {
constexpr int T = 1000, B = 256, I = 700, H = 256, O = 20, WHS = I + H;
constexpr float DELTA = 0.01f, GAMMA = 0.9f, THETA = 1.0f;
constexpr size_t OFF_LOSS = (size_t)T * B * O;
constexpr size_t OFF_ZF = OFF_LOSS + 1;
constexpr size_t OFF_UF = OFF_ZF + (size_t)B * H;
constexpr size_t OFF_OUF = OFF_UF + (size_t)B * H;

// ---- mma.sync GEMM config: single-term fp16, 128x256 CTA, x read once ----
constexpr int NCH = 22;
constexpr int WIMG = 256 * 64;
constexpr int GA = 0;
constexpr int GB = 8192;
constexpr int GSTAGE = 24576;
constexpr int GS_TOTAL = 2 * GSTAGE;

// ---- rec fallback smem ----
constexpr int REC_WZ_BYTES = 256 * 256 * 2;
constexpr int REC_SMEM = REC_WZ_BYTES + 2 * 2 * 8 * 4 + 64;

// ---- segmented ou scan ----
constexpr int NSEG = 50, SEGL = 20;
}  // namespace

__device__ float g_curx[(size_t)T * B * H];
__device__ uint32_t g_zmask[(size_t)T * B * 8];
__device__ float g_losspart[(size_t)T * B];
__device__ float g_segend[(size_t)NSEG * B * O];
__device__ float g_carry[(size_t)NSEG * B * O];
__device__ int g_spike_flag;
__device__ __align__(128) unsigned char g_wB[NCH * WIMG];

// ---------------------------------------------------------------------------
// helpers
// ---------------------------------------------------------------------------
__device__ __forceinline__ unsigned smem_u32(const void* p) {
  return (unsigned)__cvta_generic_to_shared(p);
}
__device__ __forceinline__ uint32_t pack_half2(float a, float b) {
  __half2 h = __floats2half2_rn(a, b);
  return *reinterpret_cast<uint32_t*>(&h);
}

#define LDSM4(r, addr)                                                        \
  asm volatile("ldmatrix.sync.aligned.m8n8.x4.shared.b16 {%0,%1,%2,%3}, [%4];" \
               : "=r"((r)[0]), "=r"((r)[1]), "=r"((r)[2]), "=r"((r)[3])        \
               : "r"(addr))

#define MMA16816F(d, a, b0, b1)                                               \
  asm volatile(                                                               \
      "mma.sync.aligned.m16n8k16.row.col.f32.f16.f16.f32 "                    \
      "{%0,%1,%2,%3},{%4,%5,%6,%7},{%8,%9},{%0,%1,%2,%3};"                    \
      : "+f"((d)[0]), "+f"((d)[1]), "+f"((d)[2]), "+f"((d)[3])                \
      : "r"((a)[0]), "r"((a)[1]), "r"((a)[2]), "r"((a)[3]), "r"(b0), "r"(b1))

#define CPASYNC16(dst, src)                                                   \
  asm volatile("cp.async.cg.shared.global [%0], [%1], 16;" :: "r"(dst),       \
               "l"(src) : "memory")

// ---------------------------------------------------------------------------
// Kernel 0: W_h[:, :700] -> fp16, pre-swizzled smem-image layout.
// ---------------------------------------------------------------------------
__global__ void prep_w_kernel(const float* __restrict__ Wh) {
  const int chunk = blockIdx.x;
  const int n = threadIdx.x;
  unsigned char* dst = g_wB + (size_t)chunk * WIMG + n * 64;
#pragma unroll
  for (int c = 0; c < 4; ++c) {
    uint32_t u[4];
#pragma unroll
    for (int jj = 0; jj < 4; ++jj) {
      const int k = chunk * 32 + c * 8 + jj * 2;
      float w0 = (k < I) ? Wh[(size_t)n * WHS + k] : 0.f;
      float w1 = (k + 1 < I) ? Wh[(size_t)n * WHS + k + 1] : 0.f;
      u[jj] = pack_half2(w0, w1);
    }
    const int cSw = c ^ ((n >> 1) & 3);
    *reinterpret_cast<uint4*>(dst + cSw * 16) = make_uint4(u[0], u[1], u[2], u[3]);
  }
}

// ---------------------------------------------------------------------------
// Kernel 1: cur_x = x @ W_x^T via mma.sync fp16 (passing, unchanged).
// ---------------------------------------------------------------------------
__global__ __launch_bounds__(256, 1) void gemm_mma_kernel(const float* __restrict__ X) {
  extern __shared__ __align__(1024) unsigned char smem[];
  const uint32_t sb = smem_u32(smem);
  const int tid = threadIdx.x;
  const int lane = tid & 31, wid = tid >> 5;
  const int wm = (wid & 1) * 64, wn = (wid >> 1) * 64;
  const int m0 = blockIdx.x * 128;

  const int arow = tid >> 1;
  const int aseg = (tid & 1) << 4;
  const float* xrow = X + (size_t)(m0 + arow) * I;
  const uint32_t aXor = ((arow >> 1) & 3);
  const uint32_t aDst = (uint32_t)(arow * 64);

  int raddr[4], sxa[4], rbad[4], sxb[4];
#pragma unroll
  for (int mt = 0; mt < 4; ++mt) {
    int r = wm + mt * 16 + (lane & 15);
    raddr[mt] = r * 64;
    sxa[mt] = (r >> 1) & 3;
  }
  const int ca = lane >> 4;
#pragma unroll
  for (int g = 0; g < 4; ++g) {
    int n = wn + g * 16 + (lane & 7) + ((lane >> 4) << 3);
    rbad[g] = n * 64;
    sxb[g] = (n >> 1) & 3;
  }
  const int cb = (lane >> 3) & 1;

  float acc[4][8][4];
#pragma unroll
  for (int mt = 0; mt < 4; ++mt)
#pragma unroll
    for (int n8 = 0; n8 < 8; ++n8)
#pragma unroll
      for (int j = 0; j < 4; ++j) acc[mt][n8][j] = 0.f;

  float4 av[4];

#pragma unroll
  for (int i = 0; i < 4; ++i) {
    const int col = aseg + i * 4;
    av[i] = (col < I) ? *reinterpret_cast<const float4*>(xrow + col)
                      : make_float4(0.f, 0.f, 0.f, 0.f);
  }
  {
#pragma unroll
    for (int i = 0; i < 4; ++i)
      CPASYNC16(sb + GB + tid * 16 + i * 4096, g_wB + tid * 16 + i * 4096);
    asm volatile("cp.async.commit_group;" ::: "memory");
  }
  {
#pragma unroll
    for (int half = 0; half < 2; ++half) {
      const float4 p = av[2 * half];
      const float4 q = av[2 * half + 1];
      uint32_t hu[4];
      hu[0] = pack_half2(p.x, p.y);
      hu[1] = pack_half2(p.z, p.w);
      hu[2] = pack_half2(q.x, q.y);
      hu[3] = pack_half2(q.z, q.w);
      const int cc = (aseg >> 3) + half;
      const uint32_t off = aDst + ((uint32_t)(cc ^ aXor) << 4);
      *reinterpret_cast<uint4*>(smem + GA + off) = make_uint4(hu[0], hu[1], hu[2], hu[3]);
    }
  }

  for (int c = 0; c < NCH; ++c) {
    asm volatile("cp.async.wait_group 0;" ::: "memory");
    __syncthreads();

    const int nc = c + 1;
    if (nc < NCH) {
      const uint32_t nst = sb + (nc & 1) * GSTAGE;
      const unsigned char* src = g_wB + (size_t)nc * WIMG;
#pragma unroll
      for (int i = 0; i < 4; ++i)
        CPASYNC16(nst + GB + tid * 16 + i * 4096, src + tid * 16 + i * 4096);
      asm volatile("cp.async.commit_group;" ::: "memory");
      const int colbase = nc * 32 + aseg;
#pragma unroll
      for (int i = 0; i < 4; ++i) {
        const int col = colbase + i * 4;
        av[i] = (col < I) ? *reinterpret_cast<const float4*>(xrow + col)
                          : make_float4(0.f, 0.f, 0.f, 0.f);
      }
    }

    const uint32_t st = sb + (c & 1) * GSTAGE;
#pragma unroll
    for (int k16 = 0; k16 < 2; ++k16) {
      uint32_t ah[4][4], bb[4][4];
      const int kca = k16 * 2 + ca;
      const int kcb = k16 * 2 + cb;
#pragma unroll
      for (int mt = 0; mt < 4; ++mt)
        LDSM4(ah[mt], st + GA + raddr[mt] + (((kca ^ sxa[mt])) << 4));
#pragma unroll
      for (int g = 0; g < 4; ++g)
        LDSM4(bb[g], st + GB + rbad[g] + (((kcb ^ sxb[g])) << 4));
#pragma unroll
      for (int mt = 0; mt < 4; ++mt)
#pragma unroll
        for (int g = 0; g < 4; ++g) {
          MMA16816F(acc[mt][2 * g], ah[mt], bb[g][0], bb[g][1]);
          MMA16816F(acc[mt][2 * g + 1], ah[mt], bb[g][2], bb[g][3]);
        }
    }

    if (nc < NCH) {
      unsigned char* stn = smem + (nc & 1) * GSTAGE;
#pragma unroll
      for (int half = 0; half < 2; ++half) {
        const float4 p = av[2 * half];
        const float4 q = av[2 * half + 1];
        uint32_t hu[4];
        hu[0] = pack_half2(p.x, p.y);
        hu[1] = pack_half2(p.z, p.w);
        hu[2] = pack_half2(q.x, q.y);
        hu[3] = pack_half2(q.z, q.w);
        const int cc = (aseg >> 3) + half;
        const uint32_t off = aDst + ((uint32_t)(cc ^ aXor) << 4);
        *reinterpret_cast<uint4*>(stn + GA + off) = make_uint4(hu[0], hu[1], hu[2], hu[3]);
      }
    }
  }

#pragma unroll
  for (int mt = 0; mt < 4; ++mt) {
    const int r0 = m0 + wm + mt * 16 + (lane >> 2);
#pragma unroll
    for (int n8 = 0; n8 < 8; ++n8) {
      const int col = wn + n8 * 8 + (lane & 3) * 2;
      *reinterpret_cast<float2*>(g_curx + (size_t)r0 * H + col) =
          make_float2(acc[mt][n8][0], acc[mt][n8][1]);
      *reinterpret_cast<float2*>(g_curx + (size_t)(r0 + 8) * H + col) =
          make_float2(acc[mt][n8][2], acc[mt][n8][3]);
    }
  }
}

// ---------------------------------------------------------------------------
// Kernel Z: zero the spike masks + flag (pre-speculation state).
// ---------------------------------------------------------------------------
__global__ void __launch_bounds__(256) zero_kernel() {
  const int idx = blockIdx.x * 256 + threadIdx.x;
  uint4* p = reinterpret_cast<uint4*>(g_zmask);
  if (idx < (int)(T * B * 8 / 4))
    p[idx] = make_uint4(0u, 0u, 0u, 0u);
  if (idx == 0) g_spike_flag = 0;
}

// ---------------------------------------------------------------------------
// Kernel 2a: SPECULATIVE recurrence — thread per (b,h), no barriers.
// Assumes z == 0 (no cross-h coupling); verifies via threshold check.
// Writes uf/zf; sets g_spike_flag if speculation fails anywhere.
// ---------------------------------------------------------------------------
__global__ void __launch_bounds__(256)
spec_rec_kernel(const float* __restrict__ omp, const float* __restrict__ bop,
                float* __restrict__ out) {
  const int idx = blockIdx.x * 256 + threadIdx.x;  // b*H + h
  const int h = idx & (H - 1);
  const int b = idx >> 8;

  const float om = fabsf(omp[h]);
  const float dmv = DELTA * om;
  const float pom = (-1.f + sqrtf(1.f - dmv * dmv)) / DELTA;
  const float bcoef = pom - fabsf(bop[h]);  // q == 0 under speculation

  const float* cp = g_curx + (size_t)b * H + h;
  const size_t stepstride = (size_t)B * H;

  float u = 0.f, v = 0.f;
  int spiked = 0;

  float cbuf[8], nbuf[8];
#pragma unroll
  for (int k = 0; k < 8; ++k) cbuf[k] = cp[(size_t)k * stepstride];

  for (int blk = 0; blk < T / 8; ++blk) {
    const int nb = blk + 1;
    if (nb < T / 8) {
      const float* np = cp + (size_t)nb * 8 * stepstride;
#pragma unroll
      for (int k = 0; k < 8; ++k) nbuf[k] = np[(size_t)k * stepstride];
    }
#pragma unroll
    for (int k = 0; k < 8; ++k) {
      const float un = u + DELTA * (bcoef * u - om * v + cbuf[k]);
      const float vn = v + DELTA * (om * un + bcoef * v);
      spiked |= (un - THETA - 0.f) > 0.f;
      u = un; v = vn;
    }
#pragma unroll
    for (int k = 0; k < 8; ++k) cbuf[k] = nbuf[k];
  }

  if (spiked) g_spike_flag = 1;
  out[OFF_UF + (size_t)b * H + h] = u;
  out[OFF_ZF + (size_t)b * H + h] = 0.f;
}

// ---------------------------------------------------------------------------
// Kernel 2b: serial fallback (exact, handles spikes). Early-exits if the
// speculation succeeded. Same algorithm as R12 rec_kernel.
// ---------------------------------------------------------------------------
__global__ void __launch_bounds__(256, 1)
rec_fallback_kernel(const float* __restrict__ Wh, const float* __restrict__ omp,
                    const float* __restrict__ bop, float* __restrict__ out) {
  if (g_spike_flag == 0) return;
  extern __shared__ unsigned char smrec[];
  __half* Wz = reinterpret_cast<__half*>(smrec);
  uint32_t* zms = reinterpret_cast<uint32_t*>(smrec + REC_WZ_BYTES);

  const int tid = threadIdx.x;
  const int lane = tid & 31;
  const int wq = tid >> 5;
  const int b0 = blockIdx.x * 2;

  {
    const float* src = Wh + (size_t)tid * WHS + I;
#pragma unroll 8
    for (int j = 0; j < 256; ++j) Wz[j * 256 + tid] = __float2half(src[j]);
  }
  if (tid < 32) zms[tid] = 0u;

  const float om = fabsf(omp[tid]);
  const float dmv = DELTA * om;
  const float pom = (-1.f + sqrtf(1.f - dmv * dmv)) / DELTA;
  const float bof = fabsf(bop[tid]);
  float u[2] = {0, 0}, v[2] = {0, 0}, q[2] = {0, 0}, zr[2] = {0, 0};

  __syncthreads();

  for (int t = 0; t < T; ++t) {
    const int cbuf = t & 1, nbuf = cbuf ^ 1;
    const float* cp = g_curx + ((size_t)t * B + b0) * H + tid;
    float a0 = cp[0], a1 = cp[H];

#pragma unroll
    for (int w = 0; w < 8; ++w) {
      uint32_t m = zms[(cbuf * 2 + 0) * 8 + w];
      while (m) {
        int bp = __ffs(m) - 1; m &= m - 1;
        a0 += __half2float(Wz[((w << 5) + bp) * 256 + tid]);
      }
    }
#pragma unroll
    for (int w = 0; w < 8; ++w) {
      uint32_t m = zms[(cbuf * 2 + 1) * 8 + w];
      while (m) {
        int bp = __ffs(m) - 1; m &= m - 1;
        a1 += __half2float(Wz[((w << 5) + bp) * 256 + tid]);
      }
    }

#pragma unroll
    for (int rr = 0; rr < 2; ++rr) {
      const float cw = rr ? a1 : a0;
      float b = pom - bof - q[rr];
      float un = u[rr] + DELTA * (b * u[rr] - om * v[rr] + cw);
      float vn = v[rr] + DELTA * (om * un + b * v[rr]);
      float z = (un - THETA - q[rr]) > 0.f ? 1.f : 0.f;
      q[rr] = GAMMA * q[rr] + z;
      u[rr] = un; v[rr] = vn; zr[rr] = z;
    }

    const unsigned mk0 = __ballot_sync(0xffffffffu, zr[0] > 0.f);
    const unsigned mk1 = __ballot_sync(0xffffffffu, zr[1] > 0.f);
    if (lane == 0) {
      zms[(nbuf * 2 + 0) * 8 + wq] = mk0;
      zms[(nbuf * 2 + 1) * 8 + wq] = mk1;
      g_zmask[((size_t)t * B + b0) * 8 + wq] = mk0;
      g_zmask[((size_t)t * B + b0 + 1) * 8 + wq] = mk1;
    }
    __syncthreads();
  }

#pragma unroll
  for (int rr = 0; rr < 2; ++rr) {
    const size_t idx = (size_t)(b0 + rr) * H + tid;
    out[OFF_ZF + idx] = zr[rr];
    out[OFF_UF + idx] = u[rr];
  }
}

// ---------------------------------------------------------------------------
// Kernel 3a: segment-local ou scan (unchanged).
// ---------------------------------------------------------------------------
__global__ void __launch_bounds__(256, 1)
scan_seg_kernel(const float* __restrict__ Wo, const float* __restrict__ taup,
                float* __restrict__ out) {
  __shared__ float WoT[256 * 20 + 32];
  const int tid = threadIdx.x;
  for (int i = tid; i < 256 * 20; i += 256) {
    const int j = i / 20, o = i - j * 20;
    WoT[i] = Wo[o * H + j];
  }
  __syncthreads();

  const int lid = tid & 31;
  const int gw = blockIdx.x * 8 + (tid >> 5);
  const int b = gw & (B - 1);
  const int seg = gw >> 8;
  const int t0 = seg * SEGL;
  const float alpha = (lid < 20) ? expf(-DELTA / taup[lid]) : 0.f;
  const float onem = 1.f - alpha;
  float l = 0.f;

  uint32_t mw = (lid < 8) ? g_zmask[((size_t)t0 * B + b) * 8 + lid] : 0u;
  for (int k = 0; k < SEGL; ++k) {
    const int t = t0 + k;
    uint32_t mwn = 0u;
    if (k + 1 < SEGL && lid < 8)
      mwn = g_zmask[((size_t)(t + 1) * B + b) * 8 + lid];
    float s = 0.f;
#pragma unroll
    for (int w = 0; w < 8; ++w) {
      uint32_t word = __shfl_sync(0xffffffffu, mw, w);
      while (word) {
        int bp = __ffs(word) - 1; word &= word - 1;
        s += WoT[((w << 5) + bp) * 20 + lid];
      }
    }
    l = alpha * l + onem * s;
    if (lid < 20) out[((size_t)t * B + b) * O + lid] = l;
    mw = mwn;
  }
  if (lid < 20) g_segend[((size_t)seg * B + b) * O + lid] = l;
}

// ---------------------------------------------------------------------------
// Kernel 3b: serial carry over segments (B*O threads), writes ouf.
// ---------------------------------------------------------------------------
__global__ void __launch_bounds__(256)
carry_kernel(const float* __restrict__ taup, float* __restrict__ out) {
  const int idx = blockIdx.x * 256 + threadIdx.x;
  if (idx >= B * O) return;
  const int b = idx / O, o = idx - b * O;
  const float aL = expf(-DELTA * (float)SEGL / taup[o]);
  float c = 0.f;
  for (int s = 0; s < NSEG; ++s) {
    g_carry[((size_t)s * B + b) * O + o] = c;
    c = c * aL + g_segend[((size_t)s * B + b) * O + o];
  }
  out[OFF_OUF + (size_t)b * O + o] = c;
}

// ---------------------------------------------------------------------------
// Kernel 3c: fixup — out[t,b,o] += alpha^(k+1) * carry (skip if 0).
// ---------------------------------------------------------------------------
__global__ void __launch_bounds__(256)
fixup_kernel(const float* __restrict__ taup, float* __restrict__ out) {
  const int idx = blockIdx.x * 256 + threadIdx.x;
  if (idx >= T * B * O) return;
  const int o = idx % O;
  const int tb = idx / O;
  const int t = tb / B, b = tb - t * B;
  const int seg = t / SEGL, k = t - seg * SEGL;
  const float c = g_carry[((size_t)seg * B + b) * O + o];
  if (c != 0.f) {
    const float alpha = expf(-DELTA / taup[o]);
    out[idx] += powf(alpha, (float)(k + 1)) * c;
  }
}

// ---------------------------------------------------------------------------
// Kernel 4: per-(t,b) log-softmax loss partials.
// ---------------------------------------------------------------------------
__global__ void __launch_bounds__(256)
loss_kernel(const int* __restrict__ Y, const float* __restrict__ out) {
  const int idx = blockIdx.x * 256 + threadIdx.x;
  if (idx >= T * B) return;
  const float* o20 = out + (size_t)idx * O;
  const int y = Y[idx];
  float m = -1e30f;
#pragma unroll
  for (int o = 0; o < O; ++o) m = fmaxf(m, o20[o]);
  float se = 0.f;
#pragma unroll
  for (int o = 0; o < O; ++o) se += expf(o20[o] - m);
  g_losspart[idx] = -(o20[y] - m - logf(se)) * (1.f / (float)B);
}

// ---------------------------------------------------------------------------
// Kernel 5: deterministic loss reduction.
// ---------------------------------------------------------------------------
__global__ void __launch_bounds__(1024) reduce_kernel(float* __restrict__ out) {
  __shared__ float s[1024];
  float acc = 0.f;
  for (int i = threadIdx.x; i < T * B; i += 1024) acc += g_losspart[i];
  s[threadIdx.x] = acc;
  __syncthreads();
  for (int st = 512; st > 0; st >>= 1) {
    if (threadIdx.x < st) s[threadIdx.x] += s[threadIdx.x + st];
    __syncthreads();
  }
  if (threadIdx.x == 0) out[OFF_LOSS] = s[0];
}

// ---------------------------------------------------------------------------
extern "C" void kernel_launch(void* const* d_in, const int* in_sizes, int n_in,
                              void* d_out, int out_size) {
  const float* x = (const float*)d_in[0];
  const int* y = (const int*)d_in[1];
  const float* Wh = (const float*)d_in[2];
  const float* omega = (const float*)d_in[3];
  const float* boff = (const float*)d_in[4];
  const float* Wo = (const float*)d_in[5];
  const float* tau = (const float*)d_in[6];
  float* out = (float*)d_out;

  cudaFuncSetAttribute(gemm_mma_kernel, cudaFuncAttributeMaxDynamicSharedMemorySize,
                       GS_TOTAL);
  cudaFuncSetAttribute(rec_fallback_kernel, cudaFuncAttributeMaxDynamicSharedMemorySize,
                       REC_SMEM);

  prep_w_kernel<<<NCH, 256>>>(Wh);
  gemm_mma_kernel<<<(T * B) / 128, 256, GS_TOTAL>>>(x);
  zero_kernel<<<(T * B * 8 / 4 + 255) / 256, 256>>>();
  spec_rec_kernel<<<B * H / 256, 256>>>(omega, boff, out);
  rec_fallback_kernel<<<B / 2, 256, REC_SMEM>>>(Wh, omega, boff, out);
  scan_seg_kernel<<<NSEG * B / 8, 256>>>(Wo, tau, out);
  carry_kernel<<<(B * O + 255) / 256, 256>>>(tau, out);
  fixup_kernel<<<(T * B * O + 255) / 256, 256>>>(tau, out);
  loss_kernel<<<(T * B + 255) / 256, 256>>>(y, out);
  reduce_kernel<<<1, 1024>>>(out);
}